// round 1
// baseline (speedup 1.0000x reference)
#include <cuda_runtime.h>
#include <math.h>

// Problem dims (fixed by setup_inputs)
static constexpr int BATCH = 2;
static constexpr int C_CH  = 512;
static constexpr int HDIM  = 64;
static constexpr int WDIM  = 64;
static constexpr int N_TOK = HDIM * WDIM;     // 4096
static constexpr int O3    = 3 * C_CH;        // 1536
static constexpr int NGROUPS = 32;
static constexpr int CPG   = C_CH / NGROUPS;  // 16
static constexpr float EPSV = 1e-6f;

// Scratch (static device allocations are allowed; cudaMalloc is not)
__device__ float g_hn[(size_t)BATCH * C_CH * N_TOK];        // 16 MB
__device__ float g_qkv[(size_t)BATCH * O3 * N_TOK];         // 48 MB
__device__ float g_scores[(size_t)BATCH * N_TOK * N_TOK];   // 128 MB
__device__ float g_av[(size_t)BATCH * C_CH * N_TOK];        // 16 MB
__device__ float g_stats[BATCH * NGROUPS * 2];              // mean, rstd

// ---------------------------------------------------------------------------
// GroupNorm stats: one block per (b, g); each group is a contiguous
// CPG*N_TOK = 65536-float chunk of x.
// ---------------------------------------------------------------------------
__global__ void __launch_bounds__(256) gn_stats_kernel(const float* __restrict__ x,
                                                       float* __restrict__ stats) {
    const int bg = blockIdx.x;
    const float4* p4 = (const float4*)(x + (size_t)bg * (CPG * N_TOK));
    const int t = threadIdx.x;
    float s = 0.f, ss = 0.f;
    constexpr int NV4 = CPG * N_TOK / 4;  // 16384
    for (int i = t; i < NV4; i += 256) {
        float4 v = p4[i];
        s  += v.x + v.y + v.z + v.w;
        ss += v.x * v.x + v.y * v.y + v.z * v.z + v.w * v.w;
    }
    __shared__ float shs[8], shss[8];
    #pragma unroll
    for (int o = 16; o; o >>= 1) {
        s  += __shfl_xor_sync(0xffffffffu, s, o);
        ss += __shfl_xor_sync(0xffffffffu, ss, o);
    }
    if ((t & 31) == 0) { shs[t >> 5] = s; shss[t >> 5] = ss; }
    __syncthreads();
    if (t == 0) {
        float S = 0.f, SS = 0.f;
        #pragma unroll
        for (int i = 0; i < 8; i++) { S += shs[i]; SS += shss[i]; }
        const float invn = 1.0f / (float)(CPG * N_TOK);
        float mean = S * invn;
        float var  = SS * invn - mean * mean;
        stats[bg * 2 + 0] = mean;
        stats[bg * 2 + 1] = rsqrtf(var + EPSV);
    }
}

// ---------------------------------------------------------------------------
// GroupNorm apply: hn = (x - mean) * rstd * gamma + beta  (float4 grid-stride)
// ---------------------------------------------------------------------------
__global__ void __launch_bounds__(256) gn_apply_kernel(const float* __restrict__ x,
                                                       const float* __restrict__ gamma,
                                                       const float* __restrict__ beta,
                                                       const float* __restrict__ stats,
                                                       float* __restrict__ hn) {
    const size_t i4 = (size_t)blockIdx.x * blockDim.x + threadIdx.x;
    const size_t base = i4 * 4;
    const int c = (int)((base / N_TOK) % C_CH);
    const int b = (int)(base / ((size_t)C_CH * N_TOK));
    const int bg = b * NGROUPS + c / CPG;
    const float mean = stats[bg * 2 + 0];
    const float rstd = stats[bg * 2 + 1];
    const float ga = gamma[c] * rstd;
    const float be = beta[c] - mean * ga;
    float4 v = ((const float4*)x)[i4];
    v.x = v.x * ga + be; v.y = v.y * ga + be;
    v.z = v.z * ga + be; v.w = v.w * ga + be;
    ((float4*)hn)[i4] = v;
}

// ---------------------------------------------------------------------------
// Tiled SGEMM: C[M,N] = alpha * op(A) * op(B) (+bias[row]) (+resid)
// TA=true : A stored row-major [M][K] (ld=K)   -> transpose-on-store to SMEM
// TA=false: A stored [K][M] (ld=M)             -> direct copy
// TB=true : B stored [N][K] (ld=K)             -> transpose-on-store
// TB=false: B stored [K][N] (ld=N)             -> direct copy
// BM=BN=128, BK=8, 256 threads, 8x8 per-thread register tile.
// ---------------------------------------------------------------------------
template <bool TA, bool TB, bool BIAS, bool RESID>
__global__ void __launch_bounds__(256) gemm_kernel(
    const float* __restrict__ A, const float* __restrict__ Bm,
    float* __restrict__ Cm,
    const float* __restrict__ bias, const float* __restrict__ resid,
    int M, int Nn, int K,
    long sA, long sB, long sC, long sR, float alpha) {
    constexpr int BM = 128, BN = 128, BK = 8;
    __shared__ __align__(16) float As[BK][BM];
    __shared__ __align__(16) float Bs[BK][BN];

    const int b = blockIdx.z;
    A    += (long)b * sA;
    Bm   += (long)b * sB;
    Cm   += (long)b * sC;
    const float* res = RESID ? (resid + (long)b * sR) : nullptr;

    const int bm = blockIdx.y * BM;
    const int bn = blockIdx.x * BN;
    const int t = threadIdx.x;
    const int warp = t >> 5, lane = t & 31;
    // 8 warps: 4 rows x 2 cols of 32x64 warp tiles; lane: 4x8 of 8x8 thread tiles
    const int tr = (warp >> 1) * 32 + (lane >> 3) * 8;
    const int tc = (warp & 1) * 64 + (lane & 7) * 8;

    float acc[8][8];
    #pragma unroll
    for (int i = 0; i < 8; i++)
        #pragma unroll
        for (int j = 0; j < 8; j++) acc[i][j] = 0.f;

    for (int k0 = 0; k0 < K; k0 += BK) {
        if (TA) {
            const int r = t >> 1, c4 = (t & 1) * 4;
            float4 v = *(const float4*)(A + (long)(bm + r) * K + k0 + c4);
            As[c4 + 0][r] = v.x; As[c4 + 1][r] = v.y;
            As[c4 + 2][r] = v.z; As[c4 + 3][r] = v.w;
        } else {
            const int kr = t >> 5, mc = lane * 4;
            *(float4*)&As[kr][mc] = *(const float4*)(A + (long)(k0 + kr) * M + bm + mc);
        }
        if (TB) {
            const int r = t >> 1, c4 = (t & 1) * 4;
            float4 v = *(const float4*)(Bm + (long)(bn + r) * K + k0 + c4);
            Bs[c4 + 0][r] = v.x; Bs[c4 + 1][r] = v.y;
            Bs[c4 + 2][r] = v.z; Bs[c4 + 3][r] = v.w;
        } else {
            const int kr = t >> 5, nc = lane * 4;
            *(float4*)&Bs[kr][nc] = *(const float4*)(Bm + (long)(k0 + kr) * Nn + bn + nc);
        }
        __syncthreads();

        #pragma unroll
        for (int k = 0; k < BK; k++) {
            float ar[8], br[8];
            *(float4*)&ar[0] = *(float4*)&As[k][tr];
            *(float4*)&ar[4] = *(float4*)&As[k][tr + 4];
            *(float4*)&br[0] = *(float4*)&Bs[k][tc];
            *(float4*)&br[4] = *(float4*)&Bs[k][tc + 4];
            #pragma unroll
            for (int i = 0; i < 8; i++)
                #pragma unroll
                for (int j = 0; j < 8; j++) acc[i][j] += ar[i] * br[j];
        }
        __syncthreads();
    }

    // Epilogue
    #pragma unroll
    for (int i = 0; i < 8; i++) {
        const int row = bm + tr + i;
        const float bv = BIAS ? bias[row] : 0.f;
        #pragma unroll
        for (int j = 0; j < 8; j += 4) {
            const long off = (long)row * Nn + bn + tc + j;
            float4 o;
            o.x = acc[i][j + 0] * alpha + bv;
            o.y = acc[i][j + 1] * alpha + bv;
            o.z = acc[i][j + 2] * alpha + bv;
            o.w = acc[i][j + 3] * alpha + bv;
            if (RESID) {
                float4 r = *(const float4*)(res + off);
                o.x += r.x; o.y += r.y; o.z += r.z; o.w += r.w;
            }
            *(float4*)(Cm + off) = o;
        }
    }
}

// ---------------------------------------------------------------------------
// Row softmax over contiguous last dim (length N_TOK). One block per row,
// 16 values held in registers across passes.
// ---------------------------------------------------------------------------
__global__ void __launch_bounds__(256) softmax_kernel(float* __restrict__ S) {
    float* p = S + ((size_t)blockIdx.y * N_TOK + blockIdx.x) * N_TOK;
    float4* p4 = (float4*)p;
    const int t = threadIdx.x;
    float4 v[4];
    float m = -1e30f;
    #pragma unroll
    for (int i = 0; i < 4; i++) {
        v[i] = p4[t + i * 256];
        m = fmaxf(m, fmaxf(fmaxf(v[i].x, v[i].y), fmaxf(v[i].z, v[i].w)));
    }
    __shared__ float shm[8], shsum[8];
    #pragma unroll
    for (int o = 16; o; o >>= 1) m = fmaxf(m, __shfl_xor_sync(0xffffffffu, m, o));
    if ((t & 31) == 0) shm[t >> 5] = m;
    __syncthreads();
    float bm = shm[0];
    #pragma unroll
    for (int i = 1; i < 8; i++) bm = fmaxf(bm, shm[i]);

    float s = 0.f;
    #pragma unroll
    for (int i = 0; i < 4; i++) {
        v[i].x = __expf(v[i].x - bm); v[i].y = __expf(v[i].y - bm);
        v[i].z = __expf(v[i].z - bm); v[i].w = __expf(v[i].w - bm);
        s += v[i].x + v[i].y + v[i].z + v[i].w;
    }
    #pragma unroll
    for (int o = 16; o; o >>= 1) s += __shfl_xor_sync(0xffffffffu, s, o);
    if ((t & 31) == 0) shsum[t >> 5] = s;
    __syncthreads();
    float tot = 0.f;
    #pragma unroll
    for (int i = 0; i < 8; i++) tot += shsum[i];
    const float inv = 1.0f / tot;
    #pragma unroll
    for (int i = 0; i < 4; i++) {
        v[i].x *= inv; v[i].y *= inv; v[i].z *= inv; v[i].w *= inv;
        p4[t + i * 256] = v[i];
    }
}

// ---------------------------------------------------------------------------
extern "C" void kernel_launch(void* const* d_in, const int* in_sizes, int n_in,
                              void* d_out, int out_size) {
    const float* x       = (const float*)d_in[0];
    const float* gamma   = (const float*)d_in[1];
    const float* beta    = (const float*)d_in[2];
    const float* qkv_w   = (const float*)d_in[3];
    const float* qkv_b   = (const float*)d_in[4];
    const float* proj_w  = (const float*)d_in[5];
    const float* proj_b  = (const float*)d_in[6];
    float* out = (float*)d_out;

    float *hn, *qkv, *scores, *av, *stats;
    cudaGetSymbolAddress((void**)&hn,     g_hn);
    cudaGetSymbolAddress((void**)&qkv,    g_qkv);
    cudaGetSymbolAddress((void**)&scores, g_scores);
    cudaGetSymbolAddress((void**)&av,     g_av);
    cudaGetSymbolAddress((void**)&stats,  g_stats);

    // 1) GroupNorm
    gn_stats_kernel<<<BATCH * NGROUPS, 256>>>(x, stats);
    {
        const size_t tot4 = (size_t)BATCH * C_CH * N_TOK / 4;
        gn_apply_kernel<<<(unsigned)(tot4 / 256), 256>>>(x, gamma, beta, stats, hn);
    }

    // 2) QKV: qkv[b][o][n] = qkv_w[o][c] * hn[b][c][n] + qkv_b[o]
    gemm_kernel<true, false, true, false><<<dim3(N_TOK / 128, O3 / 128, BATCH), 256>>>(
        qkv_w, hn, qkv, qkv_b, nullptr,
        O3, N_TOK, C_CH,
        0L, (long)C_CH * N_TOK, (long)O3 * N_TOK, 0L, 1.0f);

    // 3) scores[b][n][m] = scale * sum_c q[b][c][n] k[b][c][m]
    const float scale = 1.0f / sqrtf((float)C_CH);
    gemm_kernel<false, false, false, false><<<dim3(N_TOK / 128, N_TOK / 128, BATCH), 256>>>(
        qkv /* q at offset 0 */, qkv + (size_t)C_CH * N_TOK /* k */, scores,
        nullptr, nullptr,
        N_TOK, N_TOK, C_CH,
        (long)O3 * N_TOK, (long)O3 * N_TOK, (long)N_TOK * N_TOK, 0L, scale);

    // 4) softmax over m (contiguous)
    softmax_kernel<<<dim3(N_TOK, BATCH), 256>>>(scores);

    // 5) av[b][c][n] = sum_m v[b][c][m] * attn[b][n][m]
    gemm_kernel<true, true, false, false><<<dim3(N_TOK / 128, C_CH / 128, BATCH), 256>>>(
        qkv + (size_t)2 * C_CH * N_TOK /* v */, scores, av, nullptr, nullptr,
        C_CH, N_TOK, N_TOK,
        (long)O3 * N_TOK, (long)N_TOK * N_TOK, (long)C_CH * N_TOK, 0L, 1.0f);

    // 6) out = proj_w @ av + proj_b + x
    gemm_kernel<true, false, true, true><<<dim3(N_TOK / 128, C_CH / 128, BATCH), 256>>>(
        proj_w, av, out, proj_b, x,
        C_CH, N_TOK, C_CH,
        0L, (long)C_CH * N_TOK, (long)C_CH * N_TOK, (long)C_CH * N_TOK, 1.0f);
}

// round 3
// speedup vs baseline: 2.3319x; 2.3319x over previous
#include <cuda_runtime.h>
#include <math.h>
#include <stdint.h>

// Problem dims (fixed by setup_inputs)
static constexpr int BATCH = 2;
static constexpr int C_CH  = 512;
static constexpr int HDIM  = 64;
static constexpr int WDIM  = 64;
static constexpr int N_TOK = HDIM * WDIM;     // 4096
static constexpr int O3    = 3 * C_CH;        // 1536
static constexpr int NGROUPS = 32;
static constexpr int CPG   = C_CH / NGROUPS;  // 16
static constexpr float EPSV = 1e-6f;

// Scratch
__device__ float g_hn[(size_t)BATCH * C_CH * N_TOK];        // 16 MB
__device__ float g_qkv[(size_t)BATCH * O3 * N_TOK];         // 48 MB
__device__ float g_scores[(size_t)BATCH * N_TOK * N_TOK];   // 128 MB
__device__ float g_av[(size_t)BATCH * C_CH * N_TOK];        // 16 MB
__device__ float g_stats[BATCH * NGROUPS * 2];              // mean, rstd

// ---------------------------------------------------------------------------
// GroupNorm stats
// ---------------------------------------------------------------------------
__global__ void __launch_bounds__(256) gn_stats_kernel(const float* __restrict__ x,
                                                       float* __restrict__ stats) {
    const int bg = blockIdx.x;
    const float4* p4 = (const float4*)(x + (size_t)bg * (CPG * N_TOK));
    const int t = threadIdx.x;
    float s = 0.f, ss = 0.f;
    constexpr int NV4 = CPG * N_TOK / 4;
    for (int i = t; i < NV4; i += 256) {
        float4 v = p4[i];
        s  += v.x + v.y + v.z + v.w;
        ss += v.x * v.x + v.y * v.y + v.z * v.z + v.w * v.w;
    }
    __shared__ float shs[8], shss[8];
    #pragma unroll
    for (int o = 16; o; o >>= 1) {
        s  += __shfl_xor_sync(0xffffffffu, s, o);
        ss += __shfl_xor_sync(0xffffffffu, ss, o);
    }
    if ((t & 31) == 0) { shs[t >> 5] = s; shss[t >> 5] = ss; }
    __syncthreads();
    if (t == 0) {
        float S = 0.f, SS = 0.f;
        #pragma unroll
        for (int i = 0; i < 8; i++) { S += shs[i]; SS += shss[i]; }
        const float invn = 1.0f / (float)(CPG * N_TOK);
        float mean = S * invn;
        float var  = SS * invn - mean * mean;
        stats[bg * 2 + 0] = mean;
        stats[bg * 2 + 1] = rsqrtf(var + EPSV);
    }
}

// ---------------------------------------------------------------------------
// GroupNorm apply
// ---------------------------------------------------------------------------
__global__ void __launch_bounds__(256) gn_apply_kernel(const float* __restrict__ x,
                                                       const float* __restrict__ gamma,
                                                       const float* __restrict__ beta,
                                                       const float* __restrict__ stats,
                                                       float* __restrict__ hn) {
    const size_t i4 = (size_t)blockIdx.x * blockDim.x + threadIdx.x;
    const size_t base = i4 * 4;
    const int c = (int)((base / N_TOK) % C_CH);
    const int b = (int)(base / ((size_t)C_CH * N_TOK));
    const int bg = b * NGROUPS + c / CPG;
    const float mean = stats[bg * 2 + 0];
    const float rstd = stats[bg * 2 + 1];
    const float ga = gamma[c] * rstd;
    const float be = beta[c] - mean * ga;
    float4 v = ((const float4*)x)[i4];
    v.x = v.x * ga + be; v.y = v.y * ga + be;
    v.z = v.z * ga + be; v.w = v.w * ga + be;
    ((float4*)hn)[i4] = v;
}

// ---------------------------------------------------------------------------
// tf32 helpers
// ---------------------------------------------------------------------------
__device__ __forceinline__ uint32_t f2tf32(float f) {
    uint32_t r;
    asm("cvt.rna.tf32.f32 %0, %1;" : "=r"(r) : "f"(f));
    return r;
}

__device__ __forceinline__ void mma_tf32(float* d, const uint32_t* a, const uint32_t* b) {
    asm volatile(
        "mma.sync.aligned.m16n8k8.row.col.f32.tf32.tf32.f32 "
        "{%0,%1,%2,%3}, {%4,%5,%6,%7}, {%8,%9}, {%0,%1,%2,%3};"
        : "+f"(d[0]), "+f"(d[1]), "+f"(d[2]), "+f"(d[3])
        : "r"(a[0]), "r"(a[1]), "r"(a[2]), "r"(a[3]), "r"(b[0]), "r"(b[1]));
}

// ---------------------------------------------------------------------------
// Tensor-core GEMM (tf32): C[M,N] = alpha * op(A)*op(B) (+bias[row]) (+resid)
// TA=true : A row-major [M][K], row stride lda        -> transpose into smem
// TA=false: A [K][M],          row stride lda (>=M)   -> direct
// TB=true : B [N][K],          row stride ldb         -> transpose into smem
// TB=false: B [K][N],          row stride ldb (>=N)   -> direct
// BM=BN=128, BK=16, 256 threads (8 warps, 4m x 2n), warp tile 32x64.
// ---------------------------------------------------------------------------
template <bool TA, bool TB, bool BIAS, bool RESID>
__global__ void __launch_bounds__(256, 2) gemm_tc_kernel(
    const float* __restrict__ A, const float* __restrict__ Bm,
    float* __restrict__ Cm,
    const float* __restrict__ bias, const float* __restrict__ resid,
    int M, int Nn, int K, int lda, int ldb,
    long sA, long sB, long sC, long sR, float alpha) {
    constexpr int BM = 128, BN = 128, BK = 16;
    constexpr int PAD = 8;
    __shared__ __align__(16) uint32_t As[BK][BM + PAD];
    __shared__ __align__(16) uint32_t Bs[BK][BN + PAD];

    const int bz = blockIdx.z;
    A  += (long)bz * sA;
    Bm += (long)bz * sB;
    Cm += (long)bz * sC;
    const float* res = RESID ? (resid + (long)bz * sR) : nullptr;

    const int bm = blockIdx.y * BM;
    const int bn = blockIdx.x * BN;
    const int t = threadIdx.x;
    const int warp = t >> 5, lane = t & 31;
    const int g  = lane >> 2;       // group id 0..7
    const int tg = lane & 3;        // thread in group 0..3
    const int wm = (warp >> 1) * 32;   // warp m offset (4 rows)
    const int wn = (warp & 1) * 64;    // warp n offset (2 cols)

    float acc[2][8][4];
    #pragma unroll
    for (int i = 0; i < 2; i++)
        #pragma unroll
        for (int j = 0; j < 8; j++)
            #pragma unroll
            for (int q = 0; q < 4; q++) acc[i][j][q] = 0.f;

    for (int k0 = 0; k0 < K; k0 += BK) {
        // ---- load A tile ----
        if (TA) {
            // A row-major [M][K]: 2 threads per row, 8 k each; transpose
            const int r = t >> 1, kc = (t & 1) * 8;
            const float* src = A + (long)(bm + r) * lda + k0 + kc;
            float4 v0 = *(const float4*)(src);
            float4 v1 = *(const float4*)(src + 4);
            As[kc + 0][r] = f2tf32(v0.x); As[kc + 1][r] = f2tf32(v0.y);
            As[kc + 2][r] = f2tf32(v0.z); As[kc + 3][r] = f2tf32(v0.w);
            As[kc + 4][r] = f2tf32(v1.x); As[kc + 5][r] = f2tf32(v1.y);
            As[kc + 6][r] = f2tf32(v1.z); As[kc + 7][r] = f2tf32(v1.w);
        } else {
            // A [K][M]: 16 threads per k-row, 8 m each
            const int kr = t >> 4, mc = (t & 15) * 8;
            const float* src = A + (long)(k0 + kr) * lda + bm + mc;
            float4 v0 = *(const float4*)(src);
            float4 v1 = *(const float4*)(src + 4);
            uint4 o0, o1;
            o0.x = f2tf32(v0.x); o0.y = f2tf32(v0.y); o0.z = f2tf32(v0.z); o0.w = f2tf32(v0.w);
            o1.x = f2tf32(v1.x); o1.y = f2tf32(v1.y); o1.z = f2tf32(v1.z); o1.w = f2tf32(v1.w);
            *(uint4*)&As[kr][mc]     = o0;
            *(uint4*)&As[kr][mc + 4] = o1;
        }
        // ---- load B tile ----
        if (TB) {
            const int r = t >> 1, kc = (t & 1) * 8;
            const float* src = Bm + (long)(bn + r) * ldb + k0 + kc;
            float4 v0 = *(const float4*)(src);
            float4 v1 = *(const float4*)(src + 4);
            Bs[kc + 0][r] = f2tf32(v0.x); Bs[kc + 1][r] = f2tf32(v0.y);
            Bs[kc + 2][r] = f2tf32(v0.z); Bs[kc + 3][r] = f2tf32(v0.w);
            Bs[kc + 4][r] = f2tf32(v1.x); Bs[kc + 5][r] = f2tf32(v1.y);
            Bs[kc + 6][r] = f2tf32(v1.z); Bs[kc + 7][r] = f2tf32(v1.w);
        } else {
            const int kr = t >> 4, nc = (t & 15) * 8;
            const float* src = Bm + (long)(k0 + kr) * ldb + bn + nc;
            float4 v0 = *(const float4*)(src);
            float4 v1 = *(const float4*)(src + 4);
            uint4 o0, o1;
            o0.x = f2tf32(v0.x); o0.y = f2tf32(v0.y); o0.z = f2tf32(v0.z); o0.w = f2tf32(v0.w);
            o1.x = f2tf32(v1.x); o1.y = f2tf32(v1.y); o1.z = f2tf32(v1.z); o1.w = f2tf32(v1.w);
            *(uint4*)&Bs[kr][nc]     = o0;
            *(uint4*)&Bs[kr][nc + 4] = o1;
        }
        __syncthreads();

        #pragma unroll
        for (int ks = 0; ks < 2; ks++) {
            const int kb = ks * 8;
            uint32_t af[2][4];
            #pragma unroll
            for (int mt = 0; mt < 2; mt++) {
                const int m = wm + mt * 16 + g;
                af[mt][0] = As[kb + tg][m];
                af[mt][1] = As[kb + tg][m + 8];
                af[mt][2] = As[kb + 4 + tg][m];
                af[mt][3] = As[kb + 4 + tg][m + 8];
            }
            uint32_t bf[8][2];
            #pragma unroll
            for (int nt = 0; nt < 8; nt++) {
                const int n = wn + nt * 8 + g;
                bf[nt][0] = Bs[kb + tg][n];
                bf[nt][1] = Bs[kb + 4 + tg][n];
            }
            #pragma unroll
            for (int mt = 0; mt < 2; mt++)
                #pragma unroll
                for (int nt = 0; nt < 8; nt++)
                    mma_tf32(acc[mt][nt], af[mt], bf[nt]);
        }
        __syncthreads();
    }

    // ---- epilogue ----
    #pragma unroll
    for (int mt = 0; mt < 2; mt++) {
        #pragma unroll
        for (int half = 0; half < 2; half++) {
            const int row = bm + wm + mt * 16 + g + half * 8;
            const float bv = BIAS ? bias[row] : 0.f;
            #pragma unroll
            for (int nt = 0; nt < 8; nt++) {
                const int col = bn + wn + nt * 8 + tg * 2;
                const long off = (long)row * Nn + col;
                float2 o;
                o.x = acc[mt][nt][half * 2 + 0] * alpha + bv;
                o.y = acc[mt][nt][half * 2 + 1] * alpha + bv;
                if (RESID) {
                    float2 r = *(const float2*)(res + off);
                    o.x += r.x; o.y += r.y;
                }
                *(float2*)(Cm + off) = o;
            }
        }
    }
}

// ---------------------------------------------------------------------------
// Row softmax over contiguous last dim (length N_TOK).
// ---------------------------------------------------------------------------
__global__ void __launch_bounds__(256) softmax_kernel(float* __restrict__ S) {
    float* p = S + ((size_t)blockIdx.y * N_TOK + blockIdx.x) * N_TOK;
    float4* p4 = (float4*)p;
    const int t = threadIdx.x;
    float4 v[4];
    float m = -1e30f;
    #pragma unroll
    for (int i = 0; i < 4; i++) {
        v[i] = p4[t + i * 256];
        m = fmaxf(m, fmaxf(fmaxf(v[i].x, v[i].y), fmaxf(v[i].z, v[i].w)));
    }
    __shared__ float shm[8], shsum[8];
    #pragma unroll
    for (int o = 16; o; o >>= 1) m = fmaxf(m, __shfl_xor_sync(0xffffffffu, m, o));
    if ((t & 31) == 0) shm[t >> 5] = m;
    __syncthreads();
    float bm = shm[0];
    #pragma unroll
    for (int i = 1; i < 8; i++) bm = fmaxf(bm, shm[i]);

    float s = 0.f;
    #pragma unroll
    for (int i = 0; i < 4; i++) {
        v[i].x = __expf(v[i].x - bm); v[i].y = __expf(v[i].y - bm);
        v[i].z = __expf(v[i].z - bm); v[i].w = __expf(v[i].w - bm);
        s += v[i].x + v[i].y + v[i].z + v[i].w;
    }
    #pragma unroll
    for (int o = 16; o; o >>= 1) s += __shfl_xor_sync(0xffffffffu, s, o);
    if ((t & 31) == 0) shsum[t >> 5] = s;
    __syncthreads();
    float tot = 0.f;
    #pragma unroll
    for (int i = 0; i < 8; i++) tot += shsum[i];
    const float inv = 1.0f / tot;
    #pragma unroll
    for (int i = 0; i < 4; i++) {
        v[i].x *= inv; v[i].y *= inv; v[i].z *= inv; v[i].w *= inv;
        p4[t + i * 256] = v[i];
    }
}

// ---------------------------------------------------------------------------
extern "C" void kernel_launch(void* const* d_in, const int* in_sizes, int n_in,
                              void* d_out, int out_size) {
    const float* x       = (const float*)d_in[0];
    const float* gamma   = (const float*)d_in[1];
    const float* beta    = (const float*)d_in[2];
    const float* qkv_w   = (const float*)d_in[3];
    const float* qkv_b   = (const float*)d_in[4];
    const float* proj_w  = (const float*)d_in[5];
    const float* proj_b  = (const float*)d_in[6];
    float* out = (float*)d_out;

    float *hn, *qkv, *scores, *av, *stats;
    cudaGetSymbolAddress((void**)&hn,     g_hn);
    cudaGetSymbolAddress((void**)&qkv,    g_qkv);
    cudaGetSymbolAddress((void**)&scores, g_scores);
    cudaGetSymbolAddress((void**)&av,     g_av);
    cudaGetSymbolAddress((void**)&stats,  g_stats);

    // 1) GroupNorm
    gn_stats_kernel<<<BATCH * NGROUPS, 256>>>(x, stats);
    {
        const size_t tot4 = (size_t)BATCH * C_CH * N_TOK / 4;
        gn_apply_kernel<<<(unsigned)(tot4 / 256), 256>>>(x, gamma, beta, stats, hn);
    }

    // 2) QKV: qkv[b][o][n] = qkv_w[o][c] * hn[b][c][n] + qkv_b[o]
    gemm_tc_kernel<true, false, true, false><<<dim3(N_TOK / 128, O3 / 128, BATCH), 256>>>(
        qkv_w, hn, qkv, qkv_b, nullptr,
        O3, N_TOK, C_CH, C_CH, N_TOK,
        0L, (long)C_CH * N_TOK, (long)O3 * N_TOK, 0L, 1.0f);

    // 3) scores[b][n][m] = scale * sum_c q[b][c][n] k[b][c][m]
    const float scale = 1.0f / sqrtf((float)C_CH);
    gemm_tc_kernel<false, false, false, false><<<dim3(N_TOK / 128, N_TOK / 128, BATCH), 256>>>(
        qkv /* q */, qkv + (size_t)C_CH * N_TOK /* k */, scores,
        nullptr, nullptr,
        N_TOK, N_TOK, C_CH, N_TOK, N_TOK,
        (long)O3 * N_TOK, (long)O3 * N_TOK, (long)N_TOK * N_TOK, 0L, scale);

    // 4) softmax over m (contiguous)
    softmax_kernel<<<dim3(N_TOK, BATCH), 256>>>(scores);

    // 5) av[b][c][n] = sum_m v[b][c][m] * attn[b][n][m]
    gemm_tc_kernel<true, true, false, false><<<dim3(N_TOK / 128, C_CH / 128, BATCH), 256>>>(
        qkv + (size_t)2 * C_CH * N_TOK /* v */, scores, av, nullptr, nullptr,
        C_CH, N_TOK, N_TOK, N_TOK, N_TOK,
        (long)O3 * N_TOK, (long)N_TOK * N_TOK, (long)C_CH * N_TOK, 0L, 1.0f);

    // 6) out = proj_w @ av + proj_b + x
    gemm_tc_kernel<true, false, true, true><<<dim3(N_TOK / 128, C_CH / 128, BATCH), 256>>>(
        proj_w, av, out, proj_b, x,
        C_CH, N_TOK, C_CH, C_CH, N_TOK,
        0L, (long)C_CH * N_TOK, (long)C_CH * N_TOK, (long)C_CH * N_TOK, 1.0f);
}

// round 5
// speedup vs baseline: 2.8364x; 1.2163x over previous
#include <cuda_runtime.h>
#include <math.h>
#include <stdint.h>

// Problem dims (fixed by setup_inputs)
static constexpr int BATCH = 2;
static constexpr int C_CH  = 512;
static constexpr int HDIM  = 64;
static constexpr int WDIM  = 64;
static constexpr int N_TOK = HDIM * WDIM;     // 4096
static constexpr int O3    = 3 * C_CH;        // 1536
static constexpr int NGROUPS = 32;
static constexpr int CPG   = C_CH / NGROUPS;  // 16
static constexpr float EPSV = 1e-6f;

// Scratch
__device__ float g_hn[(size_t)BATCH * C_CH * N_TOK];
__device__ float g_qkv[(size_t)BATCH * O3 * N_TOK];
__device__ float g_scores[(size_t)BATCH * N_TOK * N_TOK];
__device__ float g_av[(size_t)BATCH * C_CH * N_TOK];
__device__ float g_stats[BATCH * NGROUPS * 2];

// ---------------------------------------------------------------------------
// GroupNorm stats
// ---------------------------------------------------------------------------
__global__ void __launch_bounds__(256) gn_stats_kernel(const float* __restrict__ x,
                                                       float* __restrict__ stats) {
    const int bg = blockIdx.x;
    const float4* p4 = (const float4*)(x + (size_t)bg * (CPG * N_TOK));
    const int t = threadIdx.x;
    float s = 0.f, ss = 0.f;
    constexpr int NV4 = CPG * N_TOK / 4;
    for (int i = t; i < NV4; i += 256) {
        float4 v = p4[i];
        s  += v.x + v.y + v.z + v.w;
        ss += v.x * v.x + v.y * v.y + v.z * v.z + v.w * v.w;
    }
    __shared__ float shs[8], shss[8];
    #pragma unroll
    for (int o = 16; o; o >>= 1) {
        s  += __shfl_xor_sync(0xffffffffu, s, o);
        ss += __shfl_xor_sync(0xffffffffu, ss, o);
    }
    if ((t & 31) == 0) { shs[t >> 5] = s; shss[t >> 5] = ss; }
    __syncthreads();
    if (t == 0) {
        float S = 0.f, SS = 0.f;
        #pragma unroll
        for (int i = 0; i < 8; i++) { S += shs[i]; SS += shss[i]; }
        const float invn = 1.0f / (float)(CPG * N_TOK);
        float mean = S * invn;
        float var  = SS * invn - mean * mean;
        stats[bg * 2 + 0] = mean;
        stats[bg * 2 + 1] = rsqrtf(var + EPSV);
    }
}

// ---------------------------------------------------------------------------
// GroupNorm apply
// ---------------------------------------------------------------------------
__global__ void __launch_bounds__(256) gn_apply_kernel(const float* __restrict__ x,
                                                       const float* __restrict__ gamma,
                                                       const float* __restrict__ beta,
                                                       const float* __restrict__ stats,
                                                       float* __restrict__ hn) {
    const size_t i4 = (size_t)blockIdx.x * blockDim.x + threadIdx.x;
    const size_t base = i4 * 4;
    const int c = (int)((base / N_TOK) % C_CH);
    const int b = (int)(base / ((size_t)C_CH * N_TOK));
    const int bg = b * NGROUPS + c / CPG;
    const float mean = stats[bg * 2 + 0];
    const float rstd = stats[bg * 2 + 1];
    const float ga = gamma[c] * rstd;
    const float be = beta[c] - mean * ga;
    float4 v = ((const float4*)x)[i4];
    v.x = v.x * ga + be; v.y = v.y * ga + be;
    v.z = v.z * ga + be; v.w = v.w * ga + be;
    ((float4*)hn)[i4] = v;
}

// ---------------------------------------------------------------------------
// tf32 helpers
// ---------------------------------------------------------------------------
__device__ __forceinline__ uint32_t f2tf32(float f) {
    uint32_t r;
    asm("cvt.rna.tf32.f32 %0, %1;" : "=r"(r) : "f"(f));
    return r;
}

__device__ __forceinline__ void mma_tf32(float* d, const uint32_t* a, const uint32_t* b) {
    asm volatile(
        "mma.sync.aligned.m16n8k8.row.col.f32.tf32.tf32.f32 "
        "{%0,%1,%2,%3}, {%4,%5,%6,%7}, {%8,%9}, {%0,%1,%2,%3};"
        : "+f"(d[0]), "+f"(d[1]), "+f"(d[2]), "+f"(d[3])
        : "r"(a[0]), "r"(a[1]), "r"(a[2]), "r"(a[3]), "r"(b[0]), "r"(b[1]));
}

__device__ __forceinline__ void cp16(float* dst, const float* src) {
    uint32_t d = (uint32_t)__cvta_generic_to_shared(dst);
    asm volatile("cp.async.cg.shared.global [%0], [%1], 16;\n" :: "r"(d), "l"(src));
}
__device__ __forceinline__ void cp_commit() {
    asm volatile("cp.async.commit_group;\n" ::: "memory");
}
__device__ __forceinline__ void cp_wait0() {
    asm volatile("cp.async.wait_group 0;\n" ::: "memory");
}

// ---------------------------------------------------------------------------
// Tensor-core GEMM v2: BM=128, BN=256, BK=16, 256 thr (8 warps = 2m x 4n of
// 64x64 warp tiles), cp.async 2-stage double buffer, conflict-free layouts.
// TA=true : A row-major [M][K], ld=lda -> smem [m][k]   stride 20
// TA=false: A [K][M],           ld=lda -> smem [k][m]   stride 136
// TB=true : B [N][K],           ld=ldb -> smem [n][k]   stride 20
// TB=false: B [K][N],           ld=ldb -> smem [k][n]   stride 264
// ---------------------------------------------------------------------------
constexpr int RS_RM  = 20;     // row-major tile stride (floats)
constexpr int RS_AKM = 136;    // A k-major stride
constexpr int RS_BKM = 264;    // B k-major stride
constexpr int A_WORDS = 2560;  // max(128*20, 16*136)
constexpr int B_WORDS = 5120;  // max(256*20, 16*264)
constexpr int STG_WORDS = A_WORDS + B_WORDS;          // 7680
constexpr int GEMM_SMEM = STG_WORDS * 2 * 4;          // 61440 bytes

template <bool TA, bool TB, bool BIAS, bool RESID>
__global__ void __launch_bounds__(256) gemm_tc2_kernel(
    const float* __restrict__ A, const float* __restrict__ Bm,
    float* __restrict__ Cm,
    const float* __restrict__ bias, const float* __restrict__ resid,
    int M, int Nn, int K, int lda, int ldb,
    long sA, long sB, long sC, long sR, float alpha) {
    constexpr int BM = 128, BN = 256, BK = 16;
    extern __shared__ float sm[];

    const int bz = blockIdx.z;
    A  += (long)bz * sA;
    Bm += (long)bz * sB;
    Cm += (long)bz * sC;
    const float* res = RESID ? (resid + (long)bz * sR) : nullptr;

    const int bm = blockIdx.y * BM;
    const int bn = blockIdx.x * BN;
    const int t = threadIdx.x;
    const int warp = t >> 5, lane = t & 31;
    const int g  = lane >> 2;          // 0..7
    const int tg = lane & 3;           // 0..3
    const int wm = (warp >> 2) * 64;   // 2 warp rows
    const int wn = (warp & 3) * 64;    // 4 warp cols

    float acc[4][8][4];
    #pragma unroll
    for (int i = 0; i < 4; i++)
        #pragma unroll
        for (int j = 0; j < 8; j++)
            #pragma unroll
            for (int q = 0; q < 4; q++) acc[i][j][q] = 0.f;

    auto issue_load = [&](int stg, int k0) {
        float* As = sm + stg * STG_WORDS;
        float* Bs = As + A_WORDS;
        if (TA) {
            #pragma unroll
            for (int i = 0; i < 2; i++) {
                const int tau = t + i * 256;               // 512 tasks
                const int row = tau >> 2, ch = (tau & 3) * 4;
                cp16(As + row * RS_RM + ch, A + (long)(bm + row) * lda + k0 + ch);
            }
        } else {
            #pragma unroll
            for (int i = 0; i < 2; i++) {
                const int tau = t + i * 256;
                const int kr = tau >> 5, ch = (tau & 31) * 4;
                cp16(As + kr * RS_AKM + ch, A + (long)(k0 + kr) * lda + bm + ch);
            }
        }
        if (TB) {
            #pragma unroll
            for (int i = 0; i < 4; i++) {
                const int tau = t + i * 256;               // 1024 tasks
                const int row = tau >> 2, ch = (tau & 3) * 4;
                cp16(Bs + row * RS_RM + ch, Bm + (long)(bn + row) * ldb + k0 + ch);
            }
        } else {
            #pragma unroll
            for (int i = 0; i < 4; i++) {
                const int tau = t + i * 256;
                const int kr = tau >> 6, ch = (tau & 63) * 4;
                cp16(Bs + kr * RS_BKM + ch, Bm + (long)(k0 + kr) * ldb + bn + ch);
            }
        }
        cp_commit();
    };

    issue_load(0, 0);
    const int KT = K / BK;

    for (int kt = 0; kt < KT; kt++) {
        cp_wait0();
        __syncthreads();
        if (kt + 1 < KT) issue_load((kt + 1) & 1, (kt + 1) * BK);

        const float* As = sm + (kt & 1) * STG_WORDS;
        const float* Bs = As + A_WORDS;

        #pragma unroll
        for (int ks = 0; ks < 2; ks++) {
            const int kb = ks * 8;
            uint32_t af[4][4];
            #pragma unroll
            for (int mt = 0; mt < 4; mt++) {
                const int lm = wm + mt * 16 + g;
                if (TA) {
                    af[mt][0] = f2tf32(As[lm * RS_RM + kb + tg]);
                    af[mt][1] = f2tf32(As[(lm + 8) * RS_RM + kb + tg]);
                    af[mt][2] = f2tf32(As[lm * RS_RM + kb + tg + 4]);
                    af[mt][3] = f2tf32(As[(lm + 8) * RS_RM + kb + tg + 4]);
                } else {
                    af[mt][0] = f2tf32(As[(kb + tg) * RS_AKM + lm]);
                    af[mt][1] = f2tf32(As[(kb + tg) * RS_AKM + lm + 8]);
                    af[mt][2] = f2tf32(As[(kb + tg + 4) * RS_AKM + lm]);
                    af[mt][3] = f2tf32(As[(kb + tg + 4) * RS_AKM + lm + 8]);
                }
            }
            uint32_t bf[8][2];
            #pragma unroll
            for (int nt = 0; nt < 8; nt++) {
                const int ln = wn + nt * 8 + g;
                if (TB) {
                    bf[nt][0] = f2tf32(Bs[ln * RS_RM + kb + tg]);
                    bf[nt][1] = f2tf32(Bs[ln * RS_RM + kb + tg + 4]);
                } else {
                    bf[nt][0] = f2tf32(Bs[(kb + tg) * RS_BKM + ln]);
                    bf[nt][1] = f2tf32(Bs[(kb + tg + 4) * RS_BKM + ln]);
                }
            }
            #pragma unroll
            for (int mt = 0; mt < 4; mt++)
                #pragma unroll
                for (int nt = 0; nt < 8; nt++)
                    mma_tf32(acc[mt][nt], af[mt], bf[nt]);
        }
        __syncthreads();
    }

    // ---- epilogue ----
    #pragma unroll
    for (int mt = 0; mt < 4; mt++) {
        #pragma unroll
        for (int half = 0; half < 2; half++) {
            const int row = bm + wm + mt * 16 + g + half * 8;
            const float bv = BIAS ? bias[row] : 0.f;
            #pragma unroll
            for (int nt = 0; nt < 8; nt++) {
                const int col = bn + wn + nt * 8 + tg * 2;
                const long off = (long)row * Nn + col;
                float2 o;
                o.x = acc[mt][nt][half * 2 + 0] * alpha + bv;
                o.y = acc[mt][nt][half * 2 + 1] * alpha + bv;
                if (RESID) {
                    float2 r = *(const float2*)(res + off);
                    o.x += r.x; o.y += r.y;
                }
                *(float2*)(Cm + off) = o;
            }
        }
    }
}

// ---------------------------------------------------------------------------
// Row softmax over contiguous last dim (length N_TOK).
// ---------------------------------------------------------------------------
__global__ void __launch_bounds__(256) softmax_kernel(float* __restrict__ S) {
    float* p = S + ((size_t)blockIdx.y * N_TOK + blockIdx.x) * N_TOK;
    float4* p4 = (float4*)p;
    const int t = threadIdx.x;
    float4 v[4];
    float m = -1e30f;
    #pragma unroll
    for (int i = 0; i < 4; i++) {
        v[i] = p4[t + i * 256];
        m = fmaxf(m, fmaxf(fmaxf(v[i].x, v[i].y), fmaxf(v[i].z, v[i].w)));
    }
    __shared__ float shm[8], shsum[8];
    #pragma unroll
    for (int o = 16; o; o >>= 1) m = fmaxf(m, __shfl_xor_sync(0xffffffffu, m, o));
    if ((t & 31) == 0) shm[t >> 5] = m;
    __syncthreads();
    float bm = shm[0];
    #pragma unroll
    for (int i = 1; i < 8; i++) bm = fmaxf(bm, shm[i]);

    float s = 0.f;
    #pragma unroll
    for (int i = 0; i < 4; i++) {
        v[i].x = __expf(v[i].x - bm); v[i].y = __expf(v[i].y - bm);
        v[i].z = __expf(v[i].z - bm); v[i].w = __expf(v[i].w - bm);
        s += v[i].x + v[i].y + v[i].z + v[i].w;
    }
    #pragma unroll
    for (int o = 16; o; o >>= 1) s += __shfl_xor_sync(0xffffffffu, s, o);
    if ((t & 31) == 0) shsum[t >> 5] = s;
    __syncthreads();
    float tot = 0.f;
    #pragma unroll
    for (int i = 0; i < 8; i++) tot += shsum[i];
    const float inv = 1.0f / tot;
    #pragma unroll
    for (int i = 0; i < 4; i++) {
        v[i].x *= inv; v[i].y *= inv; v[i].z *= inv; v[i].w *= inv;
        p4[t + i * 256] = v[i];
    }
}

// ---------------------------------------------------------------------------
extern "C" void kernel_launch(void* const* d_in, const int* in_sizes, int n_in,
                              void* d_out, int out_size) {
    const float* x       = (const float*)d_in[0];
    const float* gamma   = (const float*)d_in[1];
    const float* beta    = (const float*)d_in[2];
    const float* qkv_w   = (const float*)d_in[3];
    const float* qkv_b   = (const float*)d_in[4];
    const float* proj_w  = (const float*)d_in[5];
    const float* proj_b  = (const float*)d_in[6];
    float* out = (float*)d_out;

    float *hn, *qkv, *scores, *av, *stats;
    cudaGetSymbolAddress((void**)&hn,     g_hn);
    cudaGetSymbolAddress((void**)&qkv,    g_qkv);
    cudaGetSymbolAddress((void**)&scores, g_scores);
    cudaGetSymbolAddress((void**)&av,     g_av);
    cudaGetSymbolAddress((void**)&stats,  g_stats);

    // Opt in to >48KB dynamic smem (idempotent host-side attribute sets)
    cudaFuncSetAttribute(gemm_tc2_kernel<true,  false, true,  false>,
                         cudaFuncAttributeMaxDynamicSharedMemorySize, GEMM_SMEM);
    cudaFuncSetAttribute(gemm_tc2_kernel<false, false, false, false>,
                         cudaFuncAttributeMaxDynamicSharedMemorySize, GEMM_SMEM);
    cudaFuncSetAttribute(gemm_tc2_kernel<true,  true,  false, false>,
                         cudaFuncAttributeMaxDynamicSharedMemorySize, GEMM_SMEM);
    cudaFuncSetAttribute(gemm_tc2_kernel<true,  false, true,  true>,
                         cudaFuncAttributeMaxDynamicSharedMemorySize, GEMM_SMEM);

    // 1) GroupNorm
    gn_stats_kernel<<<BATCH * NGROUPS, 256>>>(x, stats);
    {
        const size_t tot4 = (size_t)BATCH * C_CH * N_TOK / 4;
        gn_apply_kernel<<<(unsigned)(tot4 / 256), 256>>>(x, gamma, beta, stats, hn);
    }

    // 2) QKV: qkv[b][o][n] = qkv_w[o][c] * hn[b][c][n] + qkv_b[o]
    gemm_tc2_kernel<true, false, true, false><<<dim3(N_TOK / 256, O3 / 128, BATCH), 256, GEMM_SMEM>>>(
        qkv_w, hn, qkv, qkv_b, nullptr,
        O3, N_TOK, C_CH, C_CH, N_TOK,
        0L, (long)C_CH * N_TOK, (long)O3 * N_TOK, 0L, 1.0f);

    // 3) scores[b][n][m] = scale * sum_c q[b][c][n] k[b][c][m]
    const float scale = 1.0f / sqrtf((float)C_CH);
    gemm_tc2_kernel<false, false, false, false><<<dim3(N_TOK / 256, N_TOK / 128, BATCH), 256, GEMM_SMEM>>>(
        qkv /* q */, qkv + (size_t)C_CH * N_TOK /* k */, scores,
        nullptr, nullptr,
        N_TOK, N_TOK, C_CH, N_TOK, N_TOK,
        (long)O3 * N_TOK, (long)O3 * N_TOK, (long)N_TOK * N_TOK, 0L, scale);

    // 4) softmax over m (contiguous)
    softmax_kernel<<<dim3(N_TOK, BATCH), 256>>>(scores);

    // 5) av[b][c][n] = sum_m v[b][c][m] * attn[b][n][m]
    gemm_tc2_kernel<true, true, false, false><<<dim3(N_TOK / 256, C_CH / 128, BATCH), 256, GEMM_SMEM>>>(
        qkv + (size_t)2 * C_CH * N_TOK /* v */, scores, av, nullptr, nullptr,
        C_CH, N_TOK, N_TOK, N_TOK, N_TOK,
        (long)O3 * N_TOK, (long)N_TOK * N_TOK, (long)C_CH * N_TOK, 0L, 1.0f);

    // 6) out = proj_w @ av + proj_b + x
    gemm_tc2_kernel<true, false, true, true><<<dim3(N_TOK / 256, C_CH / 128, BATCH), 256, GEMM_SMEM>>>(
        proj_w, av, out, proj_b, x,
        C_CH, N_TOK, C_CH, C_CH, N_TOK,
        0L, (long)C_CH * N_TOK, (long)C_CH * N_TOK, (long)C_CH * N_TOK, 1.0f);
}

// round 7
// speedup vs baseline: 2.9968x; 1.0565x over previous
#include <cuda_runtime.h>
#include <math.h>
#include <stdint.h>

// Problem dims (fixed by setup_inputs)
static constexpr int BATCH = 2;
static constexpr int C_CH  = 512;
static constexpr int HDIM  = 64;
static constexpr int WDIM  = 64;
static constexpr int N_TOK = HDIM * WDIM;     // 4096
static constexpr int O3    = 3 * C_CH;        // 1536
static constexpr int NGROUPS = 32;
static constexpr int CPG   = C_CH / NGROUPS;  // 16
static constexpr float EPSV = 1e-6f;

// Scratch
__device__ float g_hn[(size_t)BATCH * C_CH * N_TOK];
__device__ float g_qkv[(size_t)BATCH * O3 * N_TOK];
__device__ float g_scores[(size_t)BATCH * N_TOK * N_TOK];
__device__ float g_av[(size_t)BATCH * C_CH * N_TOK];
__device__ float g_stats[BATCH * NGROUPS * 2];

// ---------------------------------------------------------------------------
// GroupNorm stats
// ---------------------------------------------------------------------------
__global__ void __launch_bounds__(256) gn_stats_kernel(const float* __restrict__ x,
                                                       float* __restrict__ stats) {
    const int bg = blockIdx.x;
    const float4* p4 = (const float4*)(x + (size_t)bg * (CPG * N_TOK));
    const int t = threadIdx.x;
    float s = 0.f, ss = 0.f;
    constexpr int NV4 = CPG * N_TOK / 4;
    for (int i = t; i < NV4; i += 256) {
        float4 v = p4[i];
        s  += v.x + v.y + v.z + v.w;
        ss += v.x * v.x + v.y * v.y + v.z * v.z + v.w * v.w;
    }
    __shared__ float shs[8], shss[8];
    #pragma unroll
    for (int o = 16; o; o >>= 1) {
        s  += __shfl_xor_sync(0xffffffffu, s, o);
        ss += __shfl_xor_sync(0xffffffffu, ss, o);
    }
    if ((t & 31) == 0) { shs[t >> 5] = s; shss[t >> 5] = ss; }
    __syncthreads();
    if (t == 0) {
        float S = 0.f, SS = 0.f;
        #pragma unroll
        for (int i = 0; i < 8; i++) { S += shs[i]; SS += shss[i]; }
        const float invn = 1.0f / (float)(CPG * N_TOK);
        float mean = S * invn;
        float var  = SS * invn - mean * mean;
        stats[bg * 2 + 0] = mean;
        stats[bg * 2 + 1] = rsqrtf(var + EPSV);
    }
}

// ---------------------------------------------------------------------------
// GroupNorm apply
// ---------------------------------------------------------------------------
__global__ void __launch_bounds__(256) gn_apply_kernel(const float* __restrict__ x,
                                                       const float* __restrict__ gamma,
                                                       const float* __restrict__ beta,
                                                       const float* __restrict__ stats,
                                                       float* __restrict__ hn) {
    const size_t i4 = (size_t)blockIdx.x * blockDim.x + threadIdx.x;
    const size_t base = i4 * 4;
    const int c = (int)((base / N_TOK) % C_CH);
    const int b = (int)(base / ((size_t)C_CH * N_TOK));
    const int bg = b * NGROUPS + c / CPG;
    const float mean = stats[bg * 2 + 0];
    const float rstd = stats[bg * 2 + 1];
    const float ga = gamma[c] * rstd;
    const float be = beta[c] - mean * ga;
    float4 v = ((const float4*)x)[i4];
    v.x = v.x * ga + be; v.y = v.y * ga + be;
    v.z = v.z * ga + be; v.w = v.w * ga + be;
    ((float4*)hn)[i4] = v;
}

// ---------------------------------------------------------------------------
// mma helper (raw fp32 bits in: HMMA.tf32 uses the high 19 bits = truncation)
// ---------------------------------------------------------------------------
__device__ __forceinline__ void mma_tf32(float* d, const uint32_t* a, const uint32_t* b) {
    asm volatile(
        "mma.sync.aligned.m16n8k8.row.col.f32.tf32.tf32.f32 "
        "{%0,%1,%2,%3}, {%4,%5,%6,%7}, {%8,%9}, {%0,%1,%2,%3};"
        : "+f"(d[0]), "+f"(d[1]), "+f"(d[2]), "+f"(d[3])
        : "r"(a[0]), "r"(a[1]), "r"(a[2]), "r"(a[3]), "r"(b[0]), "r"(b[1]));
}

__device__ __forceinline__ void cp16(float* dst, const float* src) {
    uint32_t d = (uint32_t)__cvta_generic_to_shared(dst);
    asm volatile("cp.async.cg.shared.global [%0], [%1], 16;\n" :: "r"(d), "l"(src));
}
__device__ __forceinline__ void cp_commit() {
    asm volatile("cp.async.commit_group;\n" ::: "memory");
}
__device__ __forceinline__ void cp_wait0() {
    asm volatile("cp.async.wait_group 0;\n" ::: "memory");
}

// ---------------------------------------------------------------------------
// Tensor-core GEMM v3: BM=128, BN=256, BK=16, 512 thr (16 warps = 4m x 4n of
// 32x64 warp tiles), cp.async 2-stage double buffer, conflict-free strides.
// TA=true : A row-major [M][K] -> smem [m][k] stride 20
// TA=false: A [K][M]           -> smem [k][m] stride 136
// TB=true : B [N][K]           -> smem [n][k] stride 20
// TB=false: B [K][N]           -> smem [k][n] stride 264
// ---------------------------------------------------------------------------
constexpr int RS_RM  = 20;
constexpr int RS_AKM = 136;
constexpr int RS_BKM = 264;
constexpr int A_WORDS = 2560;   // max(128*20, 16*136)
constexpr int B_WORDS = 5120;   // max(256*20, 16*264)
constexpr int STG_WORDS = A_WORDS + B_WORDS;     // 7680
constexpr int GEMM_SMEM = STG_WORDS * 2 * 4;     // 61440 bytes
constexpr int GEMM_THREADS = 512;

template <bool TA, bool TB, bool BIAS, bool RESID>
__global__ void __launch_bounds__(GEMM_THREADS) gemm_tc3_kernel(
    const float* __restrict__ A, const float* __restrict__ Bm,
    float* __restrict__ Cm,
    const float* __restrict__ bias, const float* __restrict__ resid,
    int M, int Nn, int K, int lda, int ldb,
    long sA, long sB, long sC, long sR, float alpha) {
    constexpr int BM = 128, BN = 256, BK = 16;
    extern __shared__ float sm[];

    const int bz = blockIdx.z;
    A  += (long)bz * sA;
    Bm += (long)bz * sB;
    Cm += (long)bz * sC;
    const float* res = RESID ? (resid + (long)bz * sR) : nullptr;

    const int bm = blockIdx.y * BM;
    const int bn = blockIdx.x * BN;
    const int t = threadIdx.x;
    const int warp = t >> 5, lane = t & 31;
    const int g  = lane >> 2;          // 0..7
    const int tg = lane & 3;           // 0..3
    const int wm = (warp >> 2) * 32;   // 4 warp rows of 32
    const int wn = (warp & 3) * 64;    // 4 warp cols of 64

    float acc[2][8][4];
    #pragma unroll
    for (int i = 0; i < 2; i++)
        #pragma unroll
        for (int j = 0; j < 8; j++)
            #pragma unroll
            for (int q = 0; q < 4; q++) acc[i][j][q] = 0.f;

    auto issue_load = [&](int stg, int k0) {
        float* As = sm + stg * STG_WORDS;
        float* Bs = As + A_WORDS;
        if (TA) {
            // 512 tasks, 1 per thread
            const int row = t >> 2, ch = (t & 3) * 4;
            cp16(As + row * RS_RM + ch, A + (long)(bm + row) * lda + k0 + ch);
        } else {
            const int kr = t >> 5, ch = (t & 31) * 4;
            cp16(As + kr * RS_AKM + ch, A + (long)(k0 + kr) * lda + bm + ch);
        }
        if (TB) {
            // 1024 tasks, 2 per thread
            #pragma unroll
            for (int i = 0; i < 2; i++) {
                const int tau = t + i * GEMM_THREADS;
                const int row = tau >> 2, ch = (tau & 3) * 4;
                cp16(Bs + row * RS_RM + ch, Bm + (long)(bn + row) * ldb + k0 + ch);
            }
        } else {
            #pragma unroll
            for (int i = 0; i < 2; i++) {
                const int tau = t + i * GEMM_THREADS;
                const int kr = tau >> 6, ch = (tau & 63) * 4;
                cp16(Bs + kr * RS_BKM + ch, Bm + (long)(k0 + kr) * ldb + bn + ch);
            }
        }
        cp_commit();
    };

    issue_load(0, 0);
    const int KT = K / BK;

    for (int kt = 0; kt < KT; kt++) {
        cp_wait0();
        __syncthreads();
        if (kt + 1 < KT) issue_load((kt + 1) & 1, (kt + 1) * BK);

        const uint32_t* As = (const uint32_t*)(sm + (kt & 1) * STG_WORDS);
        const uint32_t* Bs = As + A_WORDS;

        #pragma unroll
        for (int ks = 0; ks < 2; ks++) {
            const int kb = ks * 8;
            uint32_t af[2][4];
            #pragma unroll
            for (int mt = 0; mt < 2; mt++) {
                const int lm = wm + mt * 16 + g;
                if (TA) {
                    af[mt][0] = As[lm * RS_RM + kb + tg];
                    af[mt][1] = As[(lm + 8) * RS_RM + kb + tg];
                    af[mt][2] = As[lm * RS_RM + kb + tg + 4];
                    af[mt][3] = As[(lm + 8) * RS_RM + kb + tg + 4];
                } else {
                    af[mt][0] = As[(kb + tg) * RS_AKM + lm];
                    af[mt][1] = As[(kb + tg) * RS_AKM + lm + 8];
                    af[mt][2] = As[(kb + tg + 4) * RS_AKM + lm];
                    af[mt][3] = As[(kb + tg + 4) * RS_AKM + lm + 8];
                }
            }
            uint32_t bf[8][2];
            #pragma unroll
            for (int nt = 0; nt < 8; nt++) {
                const int ln = wn + nt * 8 + g;
                if (TB) {
                    bf[nt][0] = Bs[ln * RS_RM + kb + tg];
                    bf[nt][1] = Bs[ln * RS_RM + kb + tg + 4];
                } else {
                    bf[nt][0] = Bs[(kb + tg) * RS_BKM + ln];
                    bf[nt][1] = Bs[(kb + tg + 4) * RS_BKM + ln];
                }
            }
            #pragma unroll
            for (int mt = 0; mt < 2; mt++)
                #pragma unroll
                for (int nt = 0; nt < 8; nt++)
                    mma_tf32(acc[mt][nt], af[mt], bf[nt]);
        }
        __syncthreads();
    }

    // ---- epilogue ----
    #pragma unroll
    for (int mt = 0; mt < 2; mt++) {
        #pragma unroll
        for (int half = 0; half < 2; half++) {
            const int row = bm + wm + mt * 16 + g + half * 8;
            const float bv = BIAS ? bias[row] : 0.f;
            #pragma unroll
            for (int nt = 0; nt < 8; nt++) {
                const int col = bn + wn + nt * 8 + tg * 2;
                const long off = (long)row * Nn + col;
                float2 o;
                o.x = acc[mt][nt][half * 2 + 0] * alpha + bv;
                o.y = acc[mt][nt][half * 2 + 1] * alpha + bv;
                if (RESID) {
                    float2 r = *(const float2*)(res + off);
                    o.x += r.x; o.y += r.y;
                }
                *(float2*)(Cm + off) = o;
            }
        }
    }
}

// ---------------------------------------------------------------------------
// Row softmax over contiguous last dim (length N_TOK).
// ---------------------------------------------------------------------------
__global__ void __launch_bounds__(256) softmax_kernel(float* __restrict__ S) {
    float* p = S + ((size_t)blockIdx.y * N_TOK + blockIdx.x) * N_TOK;
    float4* p4 = (float4*)p;
    const int t = threadIdx.x;
    float4 v[4];
    float m = -1e30f;
    #pragma unroll
    for (int i = 0; i < 4; i++) {
        v[i] = p4[t + i * 256];
        m = fmaxf(m, fmaxf(fmaxf(v[i].x, v[i].y), fmaxf(v[i].z, v[i].w)));
    }
    __shared__ float shm[8], shsum[8];
    #pragma unroll
    for (int o = 16; o; o >>= 1) m = fmaxf(m, __shfl_xor_sync(0xffffffffu, m, o));
    if ((t & 31) == 0) shm[t >> 5] = m;
    __syncthreads();
    float bm = shm[0];
    #pragma unroll
    for (int i = 1; i < 8; i++) bm = fmaxf(bm, shm[i]);

    float s = 0.f;
    #pragma unroll
    for (int i = 0; i < 4; i++) {
        v[i].x = __expf(v[i].x - bm); v[i].y = __expf(v[i].y - bm);
        v[i].z = __expf(v[i].z - bm); v[i].w = __expf(v[i].w - bm);
        s += v[i].x + v[i].y + v[i].z + v[i].w;
    }
    #pragma unroll
    for (int o = 16; o; o >>= 1) s += __shfl_xor_sync(0xffffffffu, s, o);
    if ((t & 31) == 0) shsum[t >> 5] = s;
    __syncthreads();
    float tot = 0.f;
    #pragma unroll
    for (int i = 0; i < 8; i++) tot += shsum[i];
    const float inv = 1.0f / tot;
    #pragma unroll
    for (int i = 0; i < 4; i++) {
        v[i].x *= inv; v[i].y *= inv; v[i].z *= inv; v[i].w *= inv;
        p4[t + i * 256] = v[i];
    }
}

// ---------------------------------------------------------------------------
extern "C" void kernel_launch(void* const* d_in, const int* in_sizes, int n_in,
                              void* d_out, int out_size) {
    const float* x       = (const float*)d_in[0];
    const float* gamma   = (const float*)d_in[1];
    const float* beta    = (const float*)d_in[2];
    const float* qkv_w   = (const float*)d_in[3];
    const float* qkv_b   = (const float*)d_in[4];
    const float* proj_w  = (const float*)d_in[5];
    const float* proj_b  = (const float*)d_in[6];
    float* out = (float*)d_out;

    float *hn, *qkv, *scores, *av, *stats;
    cudaGetSymbolAddress((void**)&hn,     g_hn);
    cudaGetSymbolAddress((void**)&qkv,    g_qkv);
    cudaGetSymbolAddress((void**)&scores, g_scores);
    cudaGetSymbolAddress((void**)&av,     g_av);
    cudaGetSymbolAddress((void**)&stats,  g_stats);

    cudaFuncSetAttribute(gemm_tc3_kernel<true,  false, true,  false>,
                         cudaFuncAttributeMaxDynamicSharedMemorySize, GEMM_SMEM);
    cudaFuncSetAttribute(gemm_tc3_kernel<false, false, false, false>,
                         cudaFuncAttributeMaxDynamicSharedMemorySize, GEMM_SMEM);
    cudaFuncSetAttribute(gemm_tc3_kernel<true,  true,  false, false>,
                         cudaFuncAttributeMaxDynamicSharedMemorySize, GEMM_SMEM);
    cudaFuncSetAttribute(gemm_tc3_kernel<true,  false, true,  true>,
                         cudaFuncAttributeMaxDynamicSharedMemorySize, GEMM_SMEM);

    // 1) GroupNorm
    gn_stats_kernel<<<BATCH * NGROUPS, 256>>>(x, stats);
    {
        const size_t tot4 = (size_t)BATCH * C_CH * N_TOK / 4;
        gn_apply_kernel<<<(unsigned)(tot4 / 256), 256>>>(x, gamma, beta, stats, hn);
    }

    // 2) QKV: qkv[b][o][n] = qkv_w[o][c] * hn[b][c][n] + qkv_b[o]
    gemm_tc3_kernel<true, false, true, false><<<dim3(N_TOK / 256, O3 / 128, BATCH), GEMM_THREADS, GEMM_SMEM>>>(
        qkv_w, hn, qkv, qkv_b, nullptr,
        O3, N_TOK, C_CH, C_CH, N_TOK,
        0L, (long)C_CH * N_TOK, (long)O3 * N_TOK, 0L, 1.0f);

    // 3) scores[b][n][m] = scale * sum_c q[b][c][n] k[b][c][m]
    const float scale = 1.0f / sqrtf((float)C_CH);
    gemm_tc3_kernel<false, false, false, false><<<dim3(N_TOK / 256, N_TOK / 128, BATCH), GEMM_THREADS, GEMM_SMEM>>>(
        qkv /* q */, qkv + (size_t)C_CH * N_TOK /* k */, scores,
        nullptr, nullptr,
        N_TOK, N_TOK, C_CH, N_TOK, N_TOK,
        (long)O3 * N_TOK, (long)O3 * N_TOK, (long)N_TOK * N_TOK, 0L, scale);

    // 4) softmax over m (contiguous)
    softmax_kernel<<<dim3(N_TOK, BATCH), 256>>>(scores);

    // 5) av[b][c][n] = sum_m v[b][c][m] * attn[b][n][m]
    gemm_tc3_kernel<true, true, false, false><<<dim3(N_TOK / 256, C_CH / 128, BATCH), GEMM_THREADS, GEMM_SMEM>>>(
        qkv + (size_t)2 * C_CH * N_TOK /* v */, scores, av, nullptr, nullptr,
        C_CH, N_TOK, N_TOK, N_TOK, N_TOK,
        (long)O3 * N_TOK, (long)N_TOK * N_TOK, (long)C_CH * N_TOK, 0L, 1.0f);

    // 6) out = proj_w @ av + proj_b + x
    gemm_tc3_kernel<true, false, true, true><<<dim3(N_TOK / 256, C_CH / 128, BATCH), GEMM_THREADS, GEMM_SMEM>>>(
        proj_w, av, out, proj_b, x,
        C_CH, N_TOK, C_CH, C_CH, N_TOK,
        0L, (long)C_CH * N_TOK, (long)C_CH * N_TOK, (long)C_CH * N_TOK, 1.0f);
}

// round 10
// speedup vs baseline: 3.1261x; 1.0431x over previous
#include <cuda_runtime.h>
#include <math.h>
#include <stdint.h>

// Problem dims (fixed by setup_inputs)
static constexpr int BATCH = 2;
static constexpr int C_CH  = 512;
static constexpr int HDIM  = 64;
static constexpr int WDIM  = 64;
static constexpr int N_TOK = HDIM * WDIM;     // 4096
static constexpr int O3    = 3 * C_CH;        // 1536
static constexpr int NGROUPS = 32;
static constexpr int CPG   = C_CH / NGROUPS;  // 16
static constexpr float EPSV = 1e-6f;

// Scratch
__device__ float g_hn[(size_t)BATCH * C_CH * N_TOK];
__device__ float g_qkv[(size_t)BATCH * O3 * N_TOK];
__device__ float g_scores[(size_t)BATCH * N_TOK * N_TOK];
__device__ float g_av[(size_t)BATCH * C_CH * N_TOK];
__device__ float g_stats[BATCH * NGROUPS * 2];

// ---------------------------------------------------------------------------
// GroupNorm stats
// ---------------------------------------------------------------------------
__global__ void __launch_bounds__(256) gn_stats_kernel(const float* __restrict__ x,
                                                       float* __restrict__ stats) {
    const int bg = blockIdx.x;
    const float4* p4 = (const float4*)(x + (size_t)bg * (CPG * N_TOK));
    const int t = threadIdx.x;
    float s = 0.f, ss = 0.f;
    constexpr int NV4 = CPG * N_TOK / 4;
    for (int i = t; i < NV4; i += 256) {
        float4 v = p4[i];
        s  += v.x + v.y + v.z + v.w;
        ss += v.x * v.x + v.y * v.y + v.z * v.z + v.w * v.w;
    }
    __shared__ float shs[8], shss[8];
    #pragma unroll
    for (int o = 16; o; o >>= 1) {
        s  += __shfl_xor_sync(0xffffffffu, s, o);
        ss += __shfl_xor_sync(0xffffffffu, ss, o);
    }
    if ((t & 31) == 0) { shs[t >> 5] = s; shss[t >> 5] = ss; }
    __syncthreads();
    if (t == 0) {
        float S = 0.f, SS = 0.f;
        #pragma unroll
        for (int i = 0; i < 8; i++) { S += shs[i]; SS += shss[i]; }
        const float invn = 1.0f / (float)(CPG * N_TOK);
        float mean = S * invn;
        float var  = SS * invn - mean * mean;
        stats[bg * 2 + 0] = mean;
        stats[bg * 2 + 1] = rsqrtf(var + EPSV);
    }
}

// ---------------------------------------------------------------------------
// GroupNorm apply
// ---------------------------------------------------------------------------
__global__ void __launch_bounds__(256) gn_apply_kernel(const float* __restrict__ x,
                                                       const float* __restrict__ gamma,
                                                       const float* __restrict__ beta,
                                                       const float* __restrict__ stats,
                                                       float* __restrict__ hn) {
    const size_t i4 = (size_t)blockIdx.x * blockDim.x + threadIdx.x;
    const size_t base = i4 * 4;
    const int c = (int)((base / N_TOK) % C_CH);
    const int b = (int)(base / ((size_t)C_CH * N_TOK));
    const int bg = b * NGROUPS + c / CPG;
    const float mean = stats[bg * 2 + 0];
    const float rstd = stats[bg * 2 + 1];
    const float ga = gamma[c] * rstd;
    const float be = beta[c] - mean * ga;
    float4 v = ((const float4*)x)[i4];
    v.x = v.x * ga + be; v.y = v.y * ga + be;
    v.z = v.z * ga + be; v.w = v.w * ga + be;
    ((float4*)hn)[i4] = v;
}

// ---------------------------------------------------------------------------
// mma helper (raw fp32 bits in: HMMA.tf32 uses the high 19 bits = truncation)
// ---------------------------------------------------------------------------
__device__ __forceinline__ void mma_tf32(float* d, const uint32_t* a, const uint32_t* b) {
    asm volatile(
        "mma.sync.aligned.m16n8k8.row.col.f32.tf32.tf32.f32 "
        "{%0,%1,%2,%3}, {%4,%5,%6,%7}, {%8,%9}, {%0,%1,%2,%3};"
        : "+f"(d[0]), "+f"(d[1]), "+f"(d[2]), "+f"(d[3])
        : "r"(a[0]), "r"(a[1]), "r"(a[2]), "r"(a[3]), "r"(b[0]), "r"(b[1]));
}

__device__ __forceinline__ void cp16(float* dst, const float* src) {
    uint32_t d = (uint32_t)__cvta_generic_to_shared(dst);
    asm volatile("cp.async.cg.shared.global [%0], [%1], 16;\n" :: "r"(d), "l"(src));
}
__device__ __forceinline__ void cp_commit() {
    asm volatile("cp.async.commit_group;\n" ::: "memory");
}
__device__ __forceinline__ void cp_wait0() {
    asm volatile("cp.async.wait_group 0;\n" ::: "memory");
}
__device__ __forceinline__ void cp_wait1() {
    asm volatile("cp.async.wait_group 1;\n" ::: "memory");
}

// ---------------------------------------------------------------------------
// Tensor-core GEMM v4: BM=128, BN=256, BK=16, 512 thr (16 warps = 4m x 4n of
// 32x64 warp tiles), cp.async 3-stage ring, ONE barrier per k-tile,
// conflict-free smem strides.
// TA=true : A row-major [M][K] -> smem [m][k] stride 20
// TA=false: A [K][M]           -> smem [k][m] stride 136
// TB=true : B [N][K]           -> smem [n][k] stride 20
// TB=false: B [K][N]           -> smem [k][n] stride 264
// ---------------------------------------------------------------------------
constexpr int RS_RM  = 20;
constexpr int RS_AKM = 136;
constexpr int RS_BKM = 264;
constexpr int A_WORDS = 2560;   // max(128*20, 16*136)
constexpr int B_WORDS = 5120;   // max(256*20, 16*264)
constexpr int STG_WORDS = A_WORDS + B_WORDS;     // 7680
constexpr int NSTAGE = 3;
constexpr int GEMM_SMEM = STG_WORDS * NSTAGE * 4;  // 92160 bytes
constexpr int GEMM_THREADS = 512;

template <bool TA, bool TB, bool BIAS, bool RESID>
__global__ void __launch_bounds__(GEMM_THREADS) gemm_tc4_kernel(
    const float* __restrict__ A, const float* __restrict__ Bm,
    float* __restrict__ Cm,
    const float* __restrict__ bias, const float* __restrict__ resid,
    int M, int Nn, int K, int lda, int ldb,
    long sA, long sB, long sC, long sR, float alpha) {
    constexpr int BM = 128, BN = 256, BK = 16;
    extern __shared__ float sm[];

    const int bz = blockIdx.z;
    A  += (long)bz * sA;
    Bm += (long)bz * sB;
    Cm += (long)bz * sC;
    const float* res = RESID ? (resid + (long)bz * sR) : nullptr;

    const int bm = blockIdx.y * BM;
    const int bn = blockIdx.x * BN;
    const int t = threadIdx.x;
    const int warp = t >> 5, lane = t & 31;
    const int g  = lane >> 2;          // 0..7
    const int tg = lane & 3;           // 0..3
    const int wm = (warp >> 2) * 32;   // 4 warp rows of 32
    const int wn = (warp & 3) * 64;    // 4 warp cols of 64

    float acc[2][8][4];
    #pragma unroll
    for (int i = 0; i < 2; i++)
        #pragma unroll
        for (int j = 0; j < 8; j++)
            #pragma unroll
            for (int q = 0; q < 4; q++) acc[i][j][q] = 0.f;

    auto issue_load = [&](int stg, int k0) {
        float* As = sm + stg * STG_WORDS;
        float* Bs = As + A_WORDS;
        if (TA) {
            const int row = t >> 2, ch = (t & 3) * 4;
            cp16(As + row * RS_RM + ch, A + (long)(bm + row) * lda + k0 + ch);
        } else {
            const int kr = t >> 5, ch = (t & 31) * 4;
            cp16(As + kr * RS_AKM + ch, A + (long)(k0 + kr) * lda + bm + ch);
        }
        if (TB) {
            #pragma unroll
            for (int i = 0; i < 2; i++) {
                const int tau = t + i * GEMM_THREADS;
                const int row = tau >> 2, ch = (tau & 3) * 4;
                cp16(Bs + row * RS_RM + ch, Bm + (long)(bn + row) * ldb + k0 + ch);
            }
        } else {
            #pragma unroll
            for (int i = 0; i < 2; i++) {
                const int tau = t + i * GEMM_THREADS;
                const int kr = tau >> 6, ch = (tau & 63) * 4;
                cp16(Bs + kr * RS_BKM + ch, Bm + (long)(k0 + kr) * ldb + bn + ch);
            }
        }
        cp_commit();
    };

    const int KT = K / BK;
    issue_load(0, 0);
    if (KT > 1) issue_load(1, BK);

    int stg = 0;
    for (int kt = 0; kt < KT; kt++) {
        // Need tile kt complete. In-flight: {kt, kt+1} (if issued).
        if (kt + 1 < KT) cp_wait1(); else cp_wait0();
        __syncthreads();
        // Overwrites buffer of tile kt-1; barrier above ordered all reads of it.
        if (kt + 2 < KT) {
            int nstg = stg + 2;
            if (nstg >= NSTAGE) nstg -= NSTAGE;   // proper modular wrap
            issue_load(nstg, (kt + 2) * BK);
        }

        const uint32_t* As = (const uint32_t*)(sm + stg * STG_WORDS);
        const uint32_t* Bs = As + A_WORDS;

        #pragma unroll
        for (int ks = 0; ks < 2; ks++) {
            const int kb = ks * 8;
            uint32_t af[2][4];
            #pragma unroll
            for (int mt = 0; mt < 2; mt++) {
                const int lm = wm + mt * 16 + g;
                if (TA) {
                    af[mt][0] = As[lm * RS_RM + kb + tg];
                    af[mt][1] = As[(lm + 8) * RS_RM + kb + tg];
                    af[mt][2] = As[lm * RS_RM + kb + tg + 4];
                    af[mt][3] = As[(lm + 8) * RS_RM + kb + tg + 4];
                } else {
                    af[mt][0] = As[(kb + tg) * RS_AKM + lm];
                    af[mt][1] = As[(kb + tg) * RS_AKM + lm + 8];
                    af[mt][2] = As[(kb + tg + 4) * RS_AKM + lm];
                    af[mt][3] = As[(kb + tg + 4) * RS_AKM + lm + 8];
                }
            }
            uint32_t bf[8][2];
            #pragma unroll
            for (int nt = 0; nt < 8; nt++) {
                const int ln = wn + nt * 8 + g;
                if (TB) {
                    bf[nt][0] = Bs[ln * RS_RM + kb + tg];
                    bf[nt][1] = Bs[ln * RS_RM + kb + tg + 4];
                } else {
                    bf[nt][0] = Bs[(kb + tg) * RS_BKM + ln];
                    bf[nt][1] = Bs[(kb + tg + 4) * RS_BKM + ln];
                }
            }
            #pragma unroll
            for (int mt = 0; mt < 2; mt++)
                #pragma unroll
                for (int nt = 0; nt < 8; nt++)
                    mma_tf32(acc[mt][nt], af[mt], bf[nt]);
        }
        // No trailing barrier — next iteration's load targets a stage no
        // thread is still reading (3-stage ring); top-of-loop barrier orders
        // buffer reuse.
        stg = (stg + 1 == NSTAGE) ? 0 : stg + 1;
    }

    // ---- epilogue ----
    #pragma unroll
    for (int mt = 0; mt < 2; mt++) {
        #pragma unroll
        for (int half = 0; half < 2; half++) {
            const int row = bm + wm + mt * 16 + g + half * 8;
            const float bv = BIAS ? bias[row] : 0.f;
            #pragma unroll
            for (int nt = 0; nt < 8; nt++) {
                const int col = bn + wn + nt * 8 + tg * 2;
                const long off = (long)row * Nn + col;
                float2 o;
                o.x = acc[mt][nt][half * 2 + 0] * alpha + bv;
                o.y = acc[mt][nt][half * 2 + 1] * alpha + bv;
                if (RESID) {
                    float2 r = *(const float2*)(res + off);
                    o.x += r.x; o.y += r.y;
                }
                *(float2*)(Cm + off) = o;
            }
        }
    }
}

// ---------------------------------------------------------------------------
// Row softmax over contiguous last dim (length N_TOK).
// ---------------------------------------------------------------------------
__global__ void __launch_bounds__(256) softmax_kernel(float* __restrict__ S) {
    float* p = S + ((size_t)blockIdx.y * N_TOK + blockIdx.x) * N_TOK;
    float4* p4 = (float4*)p;
    const int t = threadIdx.x;
    float4 v[4];
    float m = -1e30f;
    #pragma unroll
    for (int i = 0; i < 4; i++) {
        v[i] = p4[t + i * 256];
        m = fmaxf(m, fmaxf(fmaxf(v[i].x, v[i].y), fmaxf(v[i].z, v[i].w)));
    }
    __shared__ float shm[8], shsum[8];
    #pragma unroll
    for (int o = 16; o; o >>= 1) m = fmaxf(m, __shfl_xor_sync(0xffffffffu, m, o));
    if ((t & 31) == 0) shm[t >> 5] = m;
    __syncthreads();
    float bm = shm[0];
    #pragma unroll
    for (int i = 1; i < 8; i++) bm = fmaxf(bm, shm[i]);

    float s = 0.f;
    #pragma unroll
    for (int i = 0; i < 4; i++) {
        v[i].x = __expf(v[i].x - bm); v[i].y = __expf(v[i].y - bm);
        v[i].z = __expf(v[i].z - bm); v[i].w = __expf(v[i].w - bm);
        s += v[i].x + v[i].y + v[i].z + v[i].w;
    }
    #pragma unroll
    for (int o = 16; o; o >>= 1) s += __shfl_xor_sync(0xffffffffu, s, o);
    if ((t & 31) == 0) shsum[t >> 5] = s;
    __syncthreads();
    float tot = 0.f;
    #pragma unroll
    for (int i = 0; i < 8; i++) tot += shsum[i];
    const float inv = 1.0f / tot;
    #pragma unroll
    for (int i = 0; i < 4; i++) {
        v[i].x *= inv; v[i].y *= inv; v[i].z *= inv; v[i].w *= inv;
        p4[t + i * 256] = v[i];
    }
}

// ---------------------------------------------------------------------------
extern "C" void kernel_launch(void* const* d_in, const int* in_sizes, int n_in,
                              void* d_out, int out_size) {
    const float* x       = (const float*)d_in[0];
    const float* gamma   = (const float*)d_in[1];
    const float* beta    = (const float*)d_in[2];
    const float* qkv_w   = (const float*)d_in[3];
    const float* qkv_b   = (const float*)d_in[4];
    const float* proj_w  = (const float*)d_in[5];
    const float* proj_b  = (const float*)d_in[6];
    float* out = (float*)d_out;

    float *hn, *qkv, *scores, *av, *stats;
    cudaGetSymbolAddress((void**)&hn,     g_hn);
    cudaGetSymbolAddress((void**)&qkv,    g_qkv);
    cudaGetSymbolAddress((void**)&scores, g_scores);
    cudaGetSymbolAddress((void**)&av,     g_av);
    cudaGetSymbolAddress((void**)&stats,  g_stats);

    cudaFuncSetAttribute(gemm_tc4_kernel<true,  false, true,  false>,
                         cudaFuncAttributeMaxDynamicSharedMemorySize, GEMM_SMEM);
    cudaFuncSetAttribute(gemm_tc4_kernel<false, false, false, false>,
                         cudaFuncAttributeMaxDynamicSharedMemorySize, GEMM_SMEM);
    cudaFuncSetAttribute(gemm_tc4_kernel<true,  true,  false, false>,
                         cudaFuncAttributeMaxDynamicSharedMemorySize, GEMM_SMEM);
    cudaFuncSetAttribute(gemm_tc4_kernel<true,  false, true,  true>,
                         cudaFuncAttributeMaxDynamicSharedMemorySize, GEMM_SMEM);

    // 1) GroupNorm
    gn_stats_kernel<<<BATCH * NGROUPS, 256>>>(x, stats);
    {
        const size_t tot4 = (size_t)BATCH * C_CH * N_TOK / 4;
        gn_apply_kernel<<<(unsigned)(tot4 / 256), 256>>>(x, gamma, beta, stats, hn);
    }

    // 2) QKV: qkv[b][o][n] = qkv_w[o][c] * hn[b][c][n] + qkv_b[o]
    gemm_tc4_kernel<true, false, true, false><<<dim3(N_TOK / 256, O3 / 128, BATCH), GEMM_THREADS, GEMM_SMEM>>>(
        qkv_w, hn, qkv, qkv_b, nullptr,
        O3, N_TOK, C_CH, C_CH, N_TOK,
        0L, (long)C_CH * N_TOK, (long)O3 * N_TOK, 0L, 1.0f);

    // 3) scores[b][n][m] = scale * sum_c q[b][c][n] k[b][c][m]
    const float scale = 1.0f / sqrtf((float)C_CH);
    gemm_tc4_kernel<false, false, false, false><<<dim3(N_TOK / 256, N_TOK / 128, BATCH), GEMM_THREADS, GEMM_SMEM>>>(
        qkv /* q */, qkv + (size_t)C_CH * N_TOK /* k */, scores,
        nullptr, nullptr,
        N_TOK, N_TOK, C_CH, N_TOK, N_TOK,
        (long)O3 * N_TOK, (long)O3 * N_TOK, (long)N_TOK * N_TOK, 0L, scale);

    // 4) softmax over m (contiguous)
    softmax_kernel<<<dim3(N_TOK, BATCH), 256>>>(scores);

    // 5) av[b][c][n] = sum_m v[b][c][m] * attn[b][n][m]
    gemm_tc4_kernel<true, true, false, false><<<dim3(N_TOK / 256, C_CH / 128, BATCH), GEMM_THREADS, GEMM_SMEM>>>(
        qkv + (size_t)2 * C_CH * N_TOK /* v */, scores, av, nullptr, nullptr,
        C_CH, N_TOK, N_TOK, N_TOK, N_TOK,
        (long)O3 * N_TOK, (long)N_TOK * N_TOK, (long)C_CH * N_TOK, 0L, 1.0f);

    // 6) out = proj_w @ av + proj_b + x
    gemm_tc4_kernel<true, false, true, true><<<dim3(N_TOK / 256, C_CH / 128, BATCH), GEMM_THREADS, GEMM_SMEM>>>(
        proj_w, av, out, proj_b, x,
        C_CH, N_TOK, C_CH, C_CH, N_TOK,
        0L, (long)C_CH * N_TOK, (long)C_CH * N_TOK, (long)C_CH * N_TOK, 1.0f);
}

// round 15
// speedup vs baseline: 3.4188x; 1.0936x over previous
#include <cuda_runtime.h>
#include <math.h>
#include <stdint.h>

// Problem dims (fixed by setup_inputs)
static constexpr int BATCH = 2;
static constexpr int C_CH  = 512;
static constexpr int HDIM  = 64;
static constexpr int WDIM  = 64;
static constexpr int N_TOK = HDIM * WDIM;     // 4096
static constexpr int O3    = 3 * C_CH;        // 1536
static constexpr int NGROUPS = 32;
static constexpr int CPG   = C_CH / NGROUPS;  // 16
static constexpr float EPSV = 1e-6f;

// Scratch
__device__ float g_hn[(size_t)BATCH * C_CH * N_TOK];
__device__ float g_qkv[(size_t)BATCH * O3 * N_TOK];
__device__ float g_scores[(size_t)BATCH * N_TOK * N_TOK];
__device__ float g_av[(size_t)BATCH * C_CH * N_TOK];
__device__ float g_stats[BATCH * NGROUPS * 2];

// ---------------------------------------------------------------------------
// GroupNorm stats
// ---------------------------------------------------------------------------
__global__ void __launch_bounds__(256) gn_stats_kernel(const float* __restrict__ x,
                                                       float* __restrict__ stats) {
    const int bg = blockIdx.x;
    const float4* p4 = (const float4*)(x + (size_t)bg * (CPG * N_TOK));
    const int t = threadIdx.x;
    float s = 0.f, ss = 0.f;
    constexpr int NV4 = CPG * N_TOK / 4;
    for (int i = t; i < NV4; i += 256) {
        float4 v = p4[i];
        s  += v.x + v.y + v.z + v.w;
        ss += v.x * v.x + v.y * v.y + v.z * v.z + v.w * v.w;
    }
    __shared__ float shs[8], shss[8];
    #pragma unroll
    for (int o = 16; o; o >>= 1) {
        s  += __shfl_xor_sync(0xffffffffu, s, o);
        ss += __shfl_xor_sync(0xffffffffu, ss, o);
    }
    if ((t & 31) == 0) { shs[t >> 5] = s; shss[t >> 5] = ss; }
    __syncthreads();
    if (t == 0) {
        float S = 0.f, SS = 0.f;
        #pragma unroll
        for (int i = 0; i < 8; i++) { S += shs[i]; SS += shss[i]; }
        const float invn = 1.0f / (float)(CPG * N_TOK);
        float mean = S * invn;
        float var  = SS * invn - mean * mean;
        stats[bg * 2 + 0] = mean;
        stats[bg * 2 + 1] = rsqrtf(var + EPSV);
    }
}

// ---------------------------------------------------------------------------
// GroupNorm apply
// ---------------------------------------------------------------------------
__global__ void __launch_bounds__(256) gn_apply_kernel(const float* __restrict__ x,
                                                       const float* __restrict__ gamma,
                                                       const float* __restrict__ beta,
                                                       const float* __restrict__ stats,
                                                       float* __restrict__ hn) {
    const size_t i4 = (size_t)blockIdx.x * blockDim.x + threadIdx.x;
    const size_t base = i4 * 4;
    const int c = (int)((base / N_TOK) % C_CH);
    const int b = (int)(base / ((size_t)C_CH * N_TOK));
    const int bg = b * NGROUPS + c / CPG;
    const float mean = stats[bg * 2 + 0];
    const float rstd = stats[bg * 2 + 1];
    const float ga = gamma[c] * rstd;
    const float be = beta[c] - mean * ga;
    float4 v = ((const float4*)x)[i4];
    v.x = v.x * ga + be; v.y = v.y * ga + be;
    v.z = v.z * ga + be; v.w = v.w * ga + be;
    ((float4*)hn)[i4] = v;
}

// ---------------------------------------------------------------------------
// mma helper (raw fp32 bits in: HMMA.tf32 uses the high 19 bits = truncation)
// ---------------------------------------------------------------------------
__device__ __forceinline__ void mma_tf32(float* d, const uint32_t* a, const uint32_t* b) {
    asm volatile(
        "mma.sync.aligned.m16n8k8.row.col.f32.tf32.tf32.f32 "
        "{%0,%1,%2,%3}, {%4,%5,%6,%7}, {%8,%9}, {%0,%1,%2,%3};"
        : "+f"(d[0]), "+f"(d[1]), "+f"(d[2]), "+f"(d[3])
        : "r"(a[0]), "r"(a[1]), "r"(a[2]), "r"(a[3]), "r"(b[0]), "r"(b[1]));
}

__device__ __forceinline__ void cp16(float* dst, const float* src) {
    uint32_t d = (uint32_t)__cvta_generic_to_shared(dst);
    asm volatile("cp.async.cg.shared.global [%0], [%1], 16;\n" :: "r"(d), "l"(src));
}
__device__ __forceinline__ void cp_commit() {
    asm volatile("cp.async.commit_group;\n" ::: "memory");
}
__device__ __forceinline__ void cp_wait0() {
    asm volatile("cp.async.wait_group 0;\n" ::: "memory");
}
__device__ __forceinline__ void cp_wait1() {
    asm volatile("cp.async.wait_group 1;\n" ::: "memory");
}

// ---------------------------------------------------------------------------
// Tensor-core GEMM v5: BM=128, BN=256, BK=32, 512 thr (16 warps = 4m x 4n of
// 32x64 warp tiles), cp.async 3-stage ring, one barrier per k-tile,
// explicit per-ks fragment double-buffering (phase-overlap LDS with MMA).
// TA=true : A row-major [M][K] -> smem [m][k] stride 36
// TA=false: A [K][M]           -> smem [k][m] stride 136
// TB=true : B [N][K]           -> smem [n][k] stride 36
// TB=false: B [K][N]           -> smem [k][n] stride 264
// ---------------------------------------------------------------------------
constexpr int RS_RM  = 36;
constexpr int RS_AKM = 136;
constexpr int RS_BKM = 264;
constexpr int A_WORDS = 4608;   // max(128*36, 32*136)
constexpr int B_WORDS = 9216;   // max(256*36, 32*264)
constexpr int STG_WORDS = A_WORDS + B_WORDS;       // 13824
constexpr int NSTAGE = 3;
constexpr int GEMM_SMEM = STG_WORDS * NSTAGE * 4;  // 165888 bytes
constexpr int GEMM_THREADS = 512;

template <bool TA, bool TB, bool BIAS, bool RESID>
__global__ void __launch_bounds__(GEMM_THREADS) gemm_tc5_kernel(
    const float* __restrict__ A, const float* __restrict__ Bm,
    float* __restrict__ Cm,
    const float* __restrict__ bias, const float* __restrict__ resid,
    int M, int Nn, int K, int lda, int ldb,
    long sA, long sB, long sC, long sR, float alpha) {
    constexpr int BM = 128, BN = 256, BK = 32;
    extern __shared__ float sm[];

    const int bz = blockIdx.z;
    A  += (long)bz * sA;
    Bm += (long)bz * sB;
    Cm += (long)bz * sC;
    const float* res = RESID ? (resid + (long)bz * sR) : nullptr;

    const int bm = blockIdx.y * BM;
    const int bn = blockIdx.x * BN;
    const int t = threadIdx.x;
    const int warp = t >> 5, lane = t & 31;
    const int g  = lane >> 2;          // 0..7
    const int tg = lane & 3;           // 0..3
    const int wm = (warp >> 2) * 32;   // 4 warp rows of 32
    const int wn = (warp & 3) * 64;    // 4 warp cols of 64

    float acc[2][8][4];
    #pragma unroll
    for (int i = 0; i < 2; i++)
        #pragma unroll
        for (int j = 0; j < 8; j++)
            #pragma unroll
            for (int q = 0; q < 4; q++) acc[i][j][q] = 0.f;

    auto issue_load = [&](int stg, int k0) {
        float* As = sm + stg * STG_WORDS;
        float* Bs = As + A_WORDS;
        if (TA) {
            // 128 rows x 8 float4 chunks = 1024 tasks, 2/thread
            #pragma unroll
            for (int i = 0; i < 2; i++) {
                const int tau = t + i * GEMM_THREADS;
                const int row = tau >> 3, ch = (tau & 7) * 4;
                cp16(As + row * RS_RM + ch, A + (long)(bm + row) * lda + k0 + ch);
            }
        } else {
            // 32 k-rows x 32 chunks = 1024 tasks
            #pragma unroll
            for (int i = 0; i < 2; i++) {
                const int tau = t + i * GEMM_THREADS;
                const int kr = tau >> 5, ch = (tau & 31) * 4;
                cp16(As + kr * RS_AKM + ch, A + (long)(k0 + kr) * lda + bm + ch);
            }
        }
        if (TB) {
            // 256 rows x 8 chunks = 2048 tasks, 4/thread
            #pragma unroll
            for (int i = 0; i < 4; i++) {
                const int tau = t + i * GEMM_THREADS;
                const int row = tau >> 3, ch = (tau & 7) * 4;
                cp16(Bs + row * RS_RM + ch, Bm + (long)(bn + row) * ldb + k0 + ch);
            }
        } else {
            // 32 k-rows x 64 chunks = 2048 tasks
            #pragma unroll
            for (int i = 0; i < 4; i++) {
                const int tau = t + i * GEMM_THREADS;
                const int kr = tau >> 6, ch = (tau & 63) * 4;
                cp16(Bs + kr * RS_BKM + ch, Bm + (long)(k0 + kr) * ldb + bn + ch);
            }
        }
        cp_commit();
    };

    const int KT = K / BK;
    issue_load(0, 0);
    if (KT > 1) issue_load(1, BK);

    int stg = 0;
    for (int kt = 0; kt < KT; kt++) {
        if (kt + 1 < KT) cp_wait1(); else cp_wait0();
        __syncthreads();
        if (kt + 2 < KT) {
            int nstg = stg + 2;
            if (nstg >= NSTAGE) nstg -= NSTAGE;
            issue_load(nstg, (kt + 2) * BK);
        }

        const uint32_t* As = (const uint32_t*)(sm + stg * STG_WORDS);
        const uint32_t* Bs = As + A_WORDS;

        // Fragment loaders for ks-subtile (kb = ks*8)
        auto load_frag = [&](int ks, uint32_t afd[2][4], uint32_t bfd[8][2]) {
            const int kb = ks * 8;
            #pragma unroll
            for (int mt = 0; mt < 2; mt++) {
                const int lm = wm + mt * 16 + g;
                if (TA) {
                    afd[mt][0] = As[lm * RS_RM + kb + tg];
                    afd[mt][1] = As[(lm + 8) * RS_RM + kb + tg];
                    afd[mt][2] = As[lm * RS_RM + kb + tg + 4];
                    afd[mt][3] = As[(lm + 8) * RS_RM + kb + tg + 4];
                } else {
                    afd[mt][0] = As[(kb + tg) * RS_AKM + lm];
                    afd[mt][1] = As[(kb + tg) * RS_AKM + lm + 8];
                    afd[mt][2] = As[(kb + tg + 4) * RS_AKM + lm];
                    afd[mt][3] = As[(kb + tg + 4) * RS_AKM + lm + 8];
                }
            }
            #pragma unroll
            for (int nt = 0; nt < 8; nt++) {
                const int ln = wn + nt * 8 + g;
                if (TB) {
                    bfd[nt][0] = Bs[ln * RS_RM + kb + tg];
                    bfd[nt][1] = Bs[ln * RS_RM + kb + tg + 4];
                } else {
                    bfd[nt][0] = Bs[(kb + tg) * RS_BKM + ln];
                    bfd[nt][1] = Bs[(kb + tg + 4) * RS_BKM + ln];
                }
            }
        };

        uint32_t af[2][2][4];
        uint32_t bf[2][8][2];
        load_frag(0, af[0], bf[0]);
        #pragma unroll
        for (int ks = 0; ks < 4; ks++) {
            // Prefetch next subtile's fragments BEFORE this subtile's MMAs so
            // LDS (crossbar) overlaps tensor-pipe work instead of phasing.
            if (ks + 1 < 4) load_frag(ks + 1, af[(ks + 1) & 1], bf[(ks + 1) & 1]);
            #pragma unroll
            for (int mt = 0; mt < 2; mt++)
                #pragma unroll
                for (int nt = 0; nt < 8; nt++)
                    mma_tf32(acc[mt][nt], af[ks & 1][mt], bf[ks & 1][nt]);
        }
        stg = (stg + 1 == NSTAGE) ? 0 : stg + 1;
    }

    // ---- epilogue ----
    #pragma unroll
    for (int mt = 0; mt < 2; mt++) {
        #pragma unroll
        for (int half = 0; half < 2; half++) {
            const int row = bm + wm + mt * 16 + g + half * 8;
            const float bv = BIAS ? bias[row] : 0.f;
            #pragma unroll
            for (int nt = 0; nt < 8; nt++) {
                const int col = bn + wn + nt * 8 + tg * 2;
                const long off = (long)row * Nn + col;
                float2 o;
                o.x = acc[mt][nt][half * 2 + 0] * alpha + bv;
                o.y = acc[mt][nt][half * 2 + 1] * alpha + bv;
                if (RESID) {
                    float2 r = *(const float2*)(res + off);
                    o.x += r.x; o.y += r.y;
                }
                *(float2*)(Cm + off) = o;
            }
        }
    }
}

// ---------------------------------------------------------------------------
// Row softmax over contiguous last dim (length N_TOK).
// ---------------------------------------------------------------------------
__global__ void __launch_bounds__(256) softmax_kernel(float* __restrict__ S) {
    float* p = S + ((size_t)blockIdx.y * N_TOK + blockIdx.x) * N_TOK;
    float4* p4 = (float4*)p;
    const int t = threadIdx.x;
    float4 v[4];
    float m = -1e30f;
    #pragma unroll
    for (int i = 0; i < 4; i++) {
        v[i] = p4[t + i * 256];
        m = fmaxf(m, fmaxf(fmaxf(v[i].x, v[i].y), fmaxf(v[i].z, v[i].w)));
    }
    __shared__ float shm[8], shsum[8];
    #pragma unroll
    for (int o = 16; o; o >>= 1) m = fmaxf(m, __shfl_xor_sync(0xffffffffu, m, o));
    if ((t & 31) == 0) shm[t >> 5] = m;
    __syncthreads();
    float bm = shm[0];
    #pragma unroll
    for (int i = 1; i < 8; i++) bm = fmaxf(bm, shm[i]);

    float s = 0.f;
    #pragma unroll
    for (int i = 0; i < 4; i++) {
        v[i].x = __expf(v[i].x - bm); v[i].y = __expf(v[i].y - bm);
        v[i].z = __expf(v[i].z - bm); v[i].w = __expf(v[i].w - bm);
        s += v[i].x + v[i].y + v[i].z + v[i].w;
    }
    #pragma unroll
    for (int o = 16; o; o >>= 1) s += __shfl_xor_sync(0xffffffffu, s, o);
    if ((t & 31) == 0) shsum[t >> 5] = s;
    __syncthreads();
    float tot = 0.f;
    #pragma unroll
    for (int i = 0; i < 8; i++) tot += shsum[i];
    const float inv = 1.0f / tot;
    #pragma unroll
    for (int i = 0; i < 4; i++) {
        v[i].x *= inv; v[i].y *= inv; v[i].z *= inv; v[i].w *= inv;
        p4[t + i * 256] = v[i];
    }
}

// ---------------------------------------------------------------------------
extern "C" void kernel_launch(void* const* d_in, const int* in_sizes, int n_in,
                              void* d_out, int out_size) {
    const float* x       = (const float*)d_in[0];
    const float* gamma   = (const float*)d_in[1];
    const float* beta    = (const float*)d_in[2];
    const float* qkv_w   = (const float*)d_in[3];
    const float* qkv_b   = (const float*)d_in[4];
    const float* proj_w  = (const float*)d_in[5];
    const float* proj_b  = (const float*)d_in[6];
    float* out = (float*)d_out;

    float *hn, *qkv, *scores, *av, *stats;
    cudaGetSymbolAddress((void**)&hn,     g_hn);
    cudaGetSymbolAddress((void**)&qkv,    g_qkv);
    cudaGetSymbolAddress((void**)&scores, g_scores);
    cudaGetSymbolAddress((void**)&av,     g_av);
    cudaGetSymbolAddress((void**)&stats,  g_stats);

    cudaFuncSetAttribute(gemm_tc5_kernel<true,  false, true,  false>,
                         cudaFuncAttributeMaxDynamicSharedMemorySize, GEMM_SMEM);
    cudaFuncSetAttribute(gemm_tc5_kernel<false, false, false, false>,
                         cudaFuncAttributeMaxDynamicSharedMemorySize, GEMM_SMEM);
    cudaFuncSetAttribute(gemm_tc5_kernel<true,  true,  false, false>,
                         cudaFuncAttributeMaxDynamicSharedMemorySize, GEMM_SMEM);
    cudaFuncSetAttribute(gemm_tc5_kernel<true,  false, true,  true>,
                         cudaFuncAttributeMaxDynamicSharedMemorySize, GEMM_SMEM);

    // 1) GroupNorm
    gn_stats_kernel<<<BATCH * NGROUPS, 256>>>(x, stats);
    {
        const size_t tot4 = (size_t)BATCH * C_CH * N_TOK / 4;
        gn_apply_kernel<<<(unsigned)(tot4 / 256), 256>>>(x, gamma, beta, stats, hn);
    }

    // 2) QKV: qkv[b][o][n] = qkv_w[o][c] * hn[b][c][n] + qkv_b[o]
    gemm_tc5_kernel<true, false, true, false><<<dim3(N_TOK / 256, O3 / 128, BATCH), GEMM_THREADS, GEMM_SMEM>>>(
        qkv_w, hn, qkv, qkv_b, nullptr,
        O3, N_TOK, C_CH, C_CH, N_TOK,
        0L, (long)C_CH * N_TOK, (long)O3 * N_TOK, 0L, 1.0f);

    // 3) scores[b][n][m] = scale * sum_c q[b][c][n] k[b][c][m]
    const float scale = 1.0f / sqrtf((float)C_CH);
    gemm_tc5_kernel<false, false, false, false><<<dim3(N_TOK / 256, N_TOK / 128, BATCH), GEMM_THREADS, GEMM_SMEM>>>(
        qkv /* q */, qkv + (size_t)C_CH * N_TOK /* k */, scores,
        nullptr, nullptr,
        N_TOK, N_TOK, C_CH, N_TOK, N_TOK,
        (long)O3 * N_TOK, (long)O3 * N_TOK, (long)N_TOK * N_TOK, 0L, scale);

    // 4) softmax over m (contiguous)
    softmax_kernel<<<dim3(N_TOK, BATCH), 256>>>(scores);

    // 5) av[b][c][n] = sum_m v[b][c][m] * attn[b][n][m]
    gemm_tc5_kernel<true, true, false, false><<<dim3(N_TOK / 256, C_CH / 128, BATCH), GEMM_THREADS, GEMM_SMEM>>>(
        qkv + (size_t)2 * C_CH * N_TOK /* v */, scores, av, nullptr, nullptr,
        C_CH, N_TOK, N_TOK, N_TOK, N_TOK,
        (long)O3 * N_TOK, (long)N_TOK * N_TOK, (long)C_CH * N_TOK, 0L, 1.0f);

    // 6) out = proj_w @ av + proj_b + x
    gemm_tc5_kernel<true, false, true, true><<<dim3(N_TOK / 256, C_CH / 128, BATCH), GEMM_THREADS, GEMM_SMEM>>>(
        proj_w, av, out, proj_b, x,
        C_CH, N_TOK, C_CH, C_CH, N_TOK,
        0L, (long)C_CH * N_TOK, (long)C_CH * N_TOK, (long)C_CH * N_TOK, 1.0f);
}